// round 2
// baseline (speedup 1.0000x reference)
#include <cuda_runtime.h>
#include <math.h>

// Problem constants
#define Bc 4
#define Nc 2048
#define Dc 1024
#define Hc 8
#define HDc 64
#define FFc 4096
#define ROWS (Bc*Nc)            // 8192
#define QKVW (3*Hc*HDc)         // 1536
#define HEBW (Hc*HDc)           // 512

// ---------------- scratch (device globals; no allocs allowed) ----------------
__device__ __align__(16) float  g_V[ROWS];
__device__ __align__(16) float  g_gamma[ROWS];
__device__ __align__(16) float2 g_a[ROWS];
__device__ __align__(16) float2 g_b[ROWS];
__device__ __align__(16) float2 g_feat[ROWS];
__device__ __align__(16) float  g_x1[(size_t)ROWS*Dc];
__device__ __align__(16) float  g_xn[(size_t)ROWS*Dc];
__device__ __align__(16) float  g_qkv[(size_t)ROWS*QKVW];
__device__ __align__(16) float  g_heb[(size_t)ROWS*HEBW];
__device__ __align__(16) float  g_x2[(size_t)ROWS*Dc];
__device__ __align__(16) float  g_ffbuf[(size_t)ROWS*FFc];

// ---------------- helpers ----------------
__device__ __forceinline__ float2 blockReduce2(float a, float b) {
    // blockDim.x == 256
    #pragma unroll
    for (int off = 16; off > 0; off >>= 1) {
        a += __shfl_down_sync(0xffffffffu, a, off);
        b += __shfl_down_sync(0xffffffffu, b, off);
    }
    __shared__ float sa[8], sb[8];
    int w = threadIdx.x >> 5, l = threadIdx.x & 31;
    __syncthreads();
    if (l == 0) { sa[w] = a; sb[w] = b; }
    __syncthreads();
    if (threadIdx.x == 0) {
        float ta = sa[0], tb = sb[0];
        #pragma unroll
        for (int i = 1; i < 8; i++) { ta += sa[i]; tb += sb[i]; }
        sa[0] = ta; sb[0] = tb;
    }
    __syncthreads();
    return make_float2(sa[0], sb[0]);
}

__device__ __forceinline__ float gelu_tanh(float v) {
    const float c = 0.7978845608028654f;
    float t = tanhf(c * (v + 0.044715f * v * v * v));
    return 0.5f * v * (1.0f + t);
}

// ---------------- K1: LN1 + potential head -> V, gamma ----------------
__global__ void ln1_pot_kernel(const float* __restrict__ x,
                               const float* __restrict__ g1, const float* __restrict__ b1,
                               const float* __restrict__ wpot, const float* __restrict__ bpot) {
    int r = blockIdx.x, t = threadIdx.x;
    const float4 xv = *(const float4*)(x + (size_t)r * Dc + t * 4);
    float s  = xv.x + xv.y + xv.z + xv.w;
    float ss = xv.x*xv.x + xv.y*xv.y + xv.z*xv.z + xv.w*xv.w;
    float2 red = blockReduce2(s, ss);
    float mean = red.x * (1.0f / Dc);
    float var  = red.y * (1.0f / Dc) - mean * mean;
    float rstd = rsqrtf(var + 1e-5f);
    float4 gv = *(const float4*)(g1 + t * 4);
    float4 bv = *(const float4*)(b1 + t * 4);
    float xn0 = (xv.x - mean) * rstd * gv.x + bv.x;
    float xn1 = (xv.y - mean) * rstd * gv.y + bv.y;
    float xn2 = (xv.z - mean) * rstd * gv.z + bv.z;
    float xn3 = (xv.w - mean) * rstd * gv.w + bv.w;
    // w_pot is (D,2) row-major -> interleaved pairs
    float4 p0 = *(const float4*)(wpot + t * 8);
    float4 p1 = *(const float4*)(wpot + t * 8 + 4);
    float a0 = xn0 * p0.x + xn1 * p0.z + xn2 * p1.x + xn3 * p1.z;
    float a1 = xn0 * p0.y + xn1 * p0.w + xn2 * p1.y + xn3 * p1.w;
    float2 pr = blockReduce2(a0, a1);
    if (t == 0) {
        float Vv   = pr.x + bpot[0];
        float praw = pr.y + bpot[1];
        float sp = fmaxf(praw, 0.0f) + log1pf(__expf(-fabsf(praw)));
        g_V[r]     = Vv;
        g_gamma[r] = sp + 0.1f;
    }
}

// ---------------- K2: continued-fraction scans (8 sequential chains) ----------------
__global__ void cf_scan_kernel() {
    int id = blockIdx.x;             // 0..7
    int bb = id & 3;
    const float* Vp = g_V + bb * Nc;
    const float* Gp = g_gamma + bb * Nc;
    if (id < 4) {
        float ar = Vp[0] + 2.0f, ai = -Gp[0];
        g_a[bb * Nc + 0] = make_float2(ar, ai);
        for (int t = 1; t < Nc; t++) {
            float m  = __fdividef(1.0f, ar * ar + ai * ai);
            float dr = Vp[t] + 2.0f, di = -Gp[t];
            float nar = dr - ar * m;
            float nai = di + ai * m;
            ar = nar; ai = nai;
            g_a[bb * Nc + t] = make_float2(ar, ai);
        }
    } else {
        float br = Vp[Nc - 1] + 2.0f, bi = -Gp[Nc - 1];
        g_b[bb * Nc + Nc - 1] = make_float2(br, bi);
        for (int t = Nc - 2; t >= 0; t--) {
            float m  = __fdividef(1.0f, br * br + bi * bi);
            float dr = Vp[t] + 2.0f, di = -Gp[t];
            float nbr = dr - br * m;
            float nbi = di + bi * m;
            br = nbr; bi = nbi;
            g_b[bb * Nc + t] = make_float2(br, bi);
        }
    }
}

// ---------------- K3: G = 1/(a+b-d) -> features ----------------
__global__ void feat_kernel() {
    int i = blockIdx.x * blockDim.x + threadIdx.x;   // 8192 total
    float2 a = g_a[i], b = g_b[i];
    float dr = g_V[i] + 2.0f, di = -g_gamma[i];
    float er = a.x + b.x - dr;
    float ei = a.y + b.y - di;
    float m = __fdividef(1.0f, er * er + ei * ei);
    g_feat[i] = make_float2(er * m, -ei * m);
}

// ---------------- K4: x1 = x + feat@w_bk + b_bk ; LN2 -> g_xn ----------------
__global__ void bk_ln2_kernel(const float* __restrict__ x,
                              const float* __restrict__ wbk, const float* __restrict__ bbk,
                              const float* __restrict__ g2, const float* __restrict__ b2) {
    int r = blockIdx.x, t = threadIdx.x;
    float2 f = g_feat[r];
    const float4 xv = *(const float4*)(x + (size_t)r * Dc + t * 4);
    float4 w0 = *(const float4*)(wbk + t * 4);
    float4 w1 = *(const float4*)(wbk + Dc + t * 4);
    float4 bb = *(const float4*)(bbk + t * 4);
    float4 v;
    v.x = xv.x + f.x * w0.x + f.y * w1.x + bb.x;
    v.y = xv.y + f.x * w0.y + f.y * w1.y + bb.y;
    v.z = xv.z + f.x * w0.z + f.y * w1.z + bb.z;
    v.w = xv.w + f.x * w0.w + f.y * w1.w + bb.w;
    *(float4*)(g_x1 + (size_t)r * Dc + t * 4) = v;
    float s  = v.x + v.y + v.z + v.w;
    float ss = v.x*v.x + v.y*v.y + v.z*v.z + v.w*v.w;
    float2 red = blockReduce2(s, ss);
    float mean = red.x * (1.0f / Dc);
    float var  = red.y * (1.0f / Dc) - mean * mean;
    float rstd = rsqrtf(var + 1e-5f);
    float4 gv = *(const float4*)(g2 + t * 4);
    float4 bv = *(const float4*)(b2 + t * 4);
    float4 o;
    o.x = (v.x - mean) * rstd * gv.x + bv.x;
    o.y = (v.y - mean) * rstd * gv.y + bv.y;
    o.z = (v.z - mean) * rstd * gv.z + bv.z;
    o.w = (v.w - mean) * rstd * gv.w + bv.w;
    *(float4*)(g_xn + (size_t)r * Dc + t * 4) = o;
}

// ---------------- generic LN (for LN3) ----------------
__global__ void ln_kernel(const float* __restrict__ X,
                          const float* __restrict__ g, const float* __restrict__ b,
                          float* __restrict__ out) {
    int r = blockIdx.x, t = threadIdx.x;
    const float4 xv = *(const float4*)(X + (size_t)r * Dc + t * 4);
    float s  = xv.x + xv.y + xv.z + xv.w;
    float ss = xv.x*xv.x + xv.y*xv.y + xv.z*xv.z + xv.w*xv.w;
    float2 red = blockReduce2(s, ss);
    float mean = red.x * (1.0f / Dc);
    float var  = red.y * (1.0f / Dc) - mean * mean;
    float rstd = rsqrtf(var + 1e-5f);
    float4 gv = *(const float4*)(g + t * 4);
    float4 bv = *(const float4*)(b + t * 4);
    float4 o;
    o.x = (xv.x - mean) * rstd * gv.x + bv.x;
    o.y = (xv.y - mean) * rstd * gv.y + bv.y;
    o.z = (xv.z - mean) * rstd * gv.z + bv.z;
    o.w = (xv.w - mean) * rstd * gv.w + bv.w;
    *(float4*)(out + (size_t)r * Dc + t * 4) = o;
}

// ---------------- SGEMM: C = A(MxK) @ B(KxN) + bias [gelu] [+R] ----------------
template<int ACT, int RES>
__global__ __launch_bounds__(256, 2)
void sgemm_kernel(const float* __restrict__ A, const float* __restrict__ Bm,
                  const float* __restrict__ bias, const float* __restrict__ Rm,
                  float* __restrict__ C, int M, int Nn, int K) {
    const int BK = 8;
    __shared__ float As[BK][128];
    __shared__ float Bs[BK][128];
    int tid = threadIdx.x;
    int brow = blockIdx.y * 128;
    int bcol = blockIdx.x * 128;
    int arow = tid >> 1;
    int acol = (tid & 1) * 4;
    int brl  = tid >> 5;
    int bcl  = (tid & 31) * 4;
    int ty = tid >> 4, tx = tid & 15;
    int crow = ty * 8, ccol = tx * 8;
    float acc[8][8];
    #pragma unroll
    for (int i = 0; i < 8; i++)
        #pragma unroll
        for (int j = 0; j < 8; j++) acc[i][j] = 0.0f;

    for (int k0 = 0; k0 < K; k0 += BK) {
        float4 av = *(const float4*)(A + (size_t)(brow + arow) * K + k0 + acol);
        float4 bv = *(const float4*)(Bm + (size_t)(k0 + brl) * Nn + bcol + bcl);
        __syncthreads();
        As[acol + 0][arow] = av.x;
        As[acol + 1][arow] = av.y;
        As[acol + 2][arow] = av.z;
        As[acol + 3][arow] = av.w;
        *(float4*)&Bs[brl][bcl] = bv;
        __syncthreads();
        #pragma unroll
        for (int kk = 0; kk < BK; kk++) {
            float4 a0 = *(const float4*)&As[kk][crow];
            float4 a1 = *(const float4*)&As[kk][crow + 4];
            float4 b0 = *(const float4*)&Bs[kk][ccol];
            float4 b1 = *(const float4*)&Bs[kk][ccol + 4];
            float ar[8] = {a0.x, a0.y, a0.z, a0.w, a1.x, a1.y, a1.z, a1.w};
            float br[8] = {b0.x, b0.y, b0.z, b0.w, b1.x, b1.y, b1.z, b1.w};
            #pragma unroll
            for (int i = 0; i < 8; i++)
                #pragma unroll
                for (int j = 0; j < 8; j++)
                    acc[i][j] = fmaf(ar[i], br[j], acc[i][j]);
        }
    }
    #pragma unroll
    for (int i = 0; i < 8; i++) {
        int row = brow + crow + i;
        #pragma unroll
        for (int jb = 0; jb < 2; jb++) {
            float4 o;
            float* op = &o.x;
            #pragma unroll
            for (int j = 0; j < 4; j++) {
                int col = bcol + ccol + jb * 4 + j;
                float v = acc[i][jb * 4 + j] + bias[col];
                if (ACT) v = gelu_tanh(v);
                if (RES) v += Rm[(size_t)row * Nn + col];
                op[j] = v;
            }
            *(float4*)(C + (size_t)row * Nn + bcol + ccol + jb * 4) = o;
        }
    }
}

// ---------------- Hebbian fast-weight scan ----------------
// grid 128 blocks: (bh = blockIdx.x>>2, colgroup = blockIdx.x&3), 128 threads.
// Each warp owns 4 columns; each lane: 8 rows x 1 column of W in registers.
__global__ void __launch_bounds__(128) hebbian_kernel() {
    int bx = blockIdx.x;
    int bh = bx >> 2, cg = bx & 3;
    int b = bh >> 3, h = bh & 7;
    int tid = threadIdx.x;
    int w = tid >> 5, lane = tid & 31;
    int e  = cg * 16 + w * 4 + (lane & 3);
    int d0 = (lane >> 2) * 8;
    const float* base = g_qkv + (size_t)b * Nc * QKVW;
    const float* gp   = g_gamma + b * Nc;
    float W[8];
    #pragma unroll
    for (int i = 0; i < 8; i++) W[i] = 0.0f;

    const float* qp = base + h * 64 + d0;
    const float* kp = base + 512 + h * 64 + d0;
    const float* vp = base + 1024 + h * 64 + e;
    float4 q0 = *(const float4*)(qp);
    float4 q1 = *(const float4*)(qp + 4);
    float4 k0 = *(const float4*)(kp);
    float4 k1 = *(const float4*)(kp + 4);
    float vv = *vp;
    float* outp = g_heb + (size_t)b * Nc * HEBW + h * 64 + e;

    for (int t = 0; t < Nc; t++) {
        float4 cq0 = q0, cq1 = q1, ck0 = k0, ck1 = k1;
        float cvv = vv;
        float dec = __expf(-gp[t] * 0.01f);
        if (t + 1 < Nc) {  // prefetch next step
            const float* nb = base + (size_t)(t + 1) * QKVW;
            q0 = *(const float4*)(nb + h * 64 + d0);
            q1 = *(const float4*)(nb + h * 64 + d0 + 4);
            k0 = *(const float4*)(nb + 512 + h * 64 + d0);
            k1 = *(const float4*)(nb + 512 + h * 64 + d0 + 4);
            vv = *(nb + 1024 + h * 64 + e);
        }
        float ev = 0.1f * cvv;
        float p = 0.0f;
        W[0] = fmaf(dec, W[0], ck0.x * ev); p = fmaf(cq0.x, W[0], p);
        W[1] = fmaf(dec, W[1], ck0.y * ev); p = fmaf(cq0.y, W[1], p);
        W[2] = fmaf(dec, W[2], ck0.z * ev); p = fmaf(cq0.z, W[2], p);
        W[3] = fmaf(dec, W[3], ck0.w * ev); p = fmaf(cq0.w, W[3], p);
        W[4] = fmaf(dec, W[4], ck1.x * ev); p = fmaf(cq1.x, W[4], p);
        W[5] = fmaf(dec, W[5], ck1.y * ev); p = fmaf(cq1.y, W[5], p);
        W[6] = fmaf(dec, W[6], ck1.z * ev); p = fmaf(cq1.z, W[6], p);
        W[7] = fmaf(dec, W[7], ck1.w * ev); p = fmaf(cq1.w, W[7], p);
        p += __shfl_xor_sync(0xffffffffu, p, 4);
        p += __shfl_xor_sync(0xffffffffu, p, 8);
        p += __shfl_xor_sync(0xffffffffu, p, 16);
        if ((lane >> 2) == 0) outp[(size_t)t * HEBW] = p;
    }
}

// ---------------- host launcher ----------------
extern "C" void kernel_launch(void* const* d_in, const int* in_sizes, int n_in,
                              void* d_out, int out_size) {
    const float* x     = (const float*)d_in[0];
    const float* ln1_g = (const float*)d_in[1];
    const float* ln1_b = (const float*)d_in[2];
    const float* ln2_g = (const float*)d_in[3];
    const float* ln2_b = (const float*)d_in[4];
    const float* ln3_g = (const float*)d_in[5];
    const float* ln3_b = (const float*)d_in[6];
    const float* w_pot = (const float*)d_in[7];
    const float* b_pot = (const float*)d_in[8];
    const float* w_bk  = (const float*)d_in[9];
    const float* b_bk  = (const float*)d_in[10];
    const float* w_qkv = (const float*)d_in[11];
    const float* b_qkv = (const float*)d_in[12];
    const float* w_out = (const float*)d_in[13];
    const float* b_out = (const float*)d_in[14];
    const float* w_ff1 = (const float*)d_in[15];
    const float* b_ff1 = (const float*)d_in[16];
    const float* w_ff2 = (const float*)d_in[17];
    const float* b_ff2 = (const float*)d_in[18];

    float *pX1, *pXN, *pQKV, *pHEB, *pX2, *pFF;
    cudaGetSymbolAddress((void**)&pX1,  g_x1);
    cudaGetSymbolAddress((void**)&pXN,  g_xn);
    cudaGetSymbolAddress((void**)&pQKV, g_qkv);
    cudaGetSymbolAddress((void**)&pHEB, g_heb);
    cudaGetSymbolAddress((void**)&pX2,  g_x2);
    cudaGetSymbolAddress((void**)&pFF,  g_ffbuf);

    // 1. LN1 + potential head
    ln1_pot_kernel<<<ROWS, 256>>>(x, ln1_g, ln1_b, w_pot, b_pot);
    // 2. continued-fraction scans (fwd + bwd, 4 batches each)
    cf_scan_kernel<<<8, 1>>>();
    // 3. Green-function diagonal features
    feat_kernel<<<32, 256>>>();
    // 4. rank-2 injection + LN2
    bk_ln2_kernel<<<ROWS, 256>>>(x, w_bk, b_bk, ln2_g, ln2_b);
    // 5. QKV projection
    sgemm_kernel<0, 0><<<dim3(QKVW / 128, ROWS / 128), 256>>>(
        pXN, w_qkv, b_qkv, nullptr, pQKV, ROWS, QKVW, Dc);
    // 6. Hebbian fast-weight scan
    hebbian_kernel<<<128, 128>>>();
    // 7. out-projection + residual(x1)
    sgemm_kernel<0, 1><<<dim3(Dc / 128, ROWS / 128), 256>>>(
        pHEB, w_out, b_out, pX1, pX2, ROWS, Dc, HEBW);
    // 8. LN3
    ln_kernel<<<ROWS, 256>>>(pX2, ln3_g, ln3_b, pXN);
    // 9. FFN up + gelu
    sgemm_kernel<1, 0><<<dim3(FFc / 128, ROWS / 128), 256>>>(
        pXN, w_ff1, b_ff1, nullptr, pFF, ROWS, FFc, Dc);
    // 10. FFN down + residual(x2) -> output
    sgemm_kernel<0, 1><<<dim3(Dc / 128, ROWS / 128), 256>>>(
        pFF, w_ff2, b_ff2, pX2, (float*)d_out, ROWS, Dc, FFc);
}

// round 3
// speedup vs baseline: 1.7812x; 1.7812x over previous
#include <cuda_runtime.h>
#include <math.h>

// Problem constants
#define Bc 4
#define Nc 2048
#define Dc 1024
#define Hc 8
#define HDc 64
#define FFc 4096
#define ROWS (Bc*Nc)            // 8192
#define QKVW (3*Hc*HDc)         // 1536
#define HEBW (Hc*HDc)           // 512

// ---------------- scratch (device globals; no allocs allowed) ----------------
__device__ __align__(16) float  g_V[ROWS];
__device__ __align__(16) float  g_gamma[ROWS];
__device__ __align__(16) float2 g_a[ROWS];
__device__ __align__(16) float2 g_b[ROWS];
__device__ __align__(16) float2 g_feat[ROWS];
__device__ __align__(16) float  g_x1[(size_t)ROWS*Dc];
__device__ __align__(16) float  g_xn[(size_t)ROWS*Dc];
__device__ __align__(16) float  g_qkv[(size_t)ROWS*QKVW];
__device__ __align__(16) float  g_heb[(size_t)ROWS*HEBW];
__device__ __align__(16) float  g_x2[(size_t)ROWS*Dc];
__device__ __align__(16) float  g_ffbuf[(size_t)ROWS*FFc];

// ---------------- helpers ----------------
__device__ __forceinline__ float2 blockReduce2(float a, float b) {
    // blockDim.x == 256
    #pragma unroll
    for (int off = 16; off > 0; off >>= 1) {
        a += __shfl_down_sync(0xffffffffu, a, off);
        b += __shfl_down_sync(0xffffffffu, b, off);
    }
    __shared__ float sa[8], sb[8];
    int w = threadIdx.x >> 5, l = threadIdx.x & 31;
    __syncthreads();
    if (l == 0) { sa[w] = a; sb[w] = b; }
    __syncthreads();
    if (threadIdx.x == 0) {
        float ta = sa[0], tb = sb[0];
        #pragma unroll
        for (int i = 1; i < 8; i++) { ta += sa[i]; tb += sb[i]; }
        sa[0] = ta; sb[0] = tb;
    }
    __syncthreads();
    return make_float2(sa[0], sb[0]);
}

__device__ __forceinline__ float gelu_tanh(float v) {
    const float c = 0.7978845608028654f;
    float t = tanhf(c * (v + 0.044715f * v * v * v));
    return 0.5f * v * (1.0f + t);
}

__device__ __forceinline__ unsigned f2tf(float x) {
    unsigned r;
    asm("cvt.rna.tf32.f32 %0, %1;" : "=r"(r) : "f"(x));
    return r;
}

__device__ __forceinline__ void mma_tf32(float* d, const unsigned* a, const unsigned* b) {
    asm volatile(
        "mma.sync.aligned.m16n8k8.row.col.f32.tf32.tf32.f32 "
        "{%0,%1,%2,%3}, {%4,%5,%6,%7}, {%8,%9}, {%0,%1,%2,%3};"
        : "+f"(d[0]), "+f"(d[1]), "+f"(d[2]), "+f"(d[3])
        : "r"(a[0]), "r"(a[1]), "r"(a[2]), "r"(a[3]), "r"(b[0]), "r"(b[1]));
}

// ---------------- K1: LN1 + potential head -> V, gamma ----------------
__global__ void ln1_pot_kernel(const float* __restrict__ x,
                               const float* __restrict__ g1, const float* __restrict__ b1,
                               const float* __restrict__ wpot, const float* __restrict__ bpot) {
    int r = blockIdx.x, t = threadIdx.x;
    const float4 xv = *(const float4*)(x + (size_t)r * Dc + t * 4);
    float s  = xv.x + xv.y + xv.z + xv.w;
    float ss = xv.x*xv.x + xv.y*xv.y + xv.z*xv.z + xv.w*xv.w;
    float2 red = blockReduce2(s, ss);
    float mean = red.x * (1.0f / Dc);
    float var  = red.y * (1.0f / Dc) - mean * mean;
    float rstd = rsqrtf(var + 1e-5f);
    float4 gv = *(const float4*)(g1 + t * 4);
    float4 bv = *(const float4*)(b1 + t * 4);
    float xn0 = (xv.x - mean) * rstd * gv.x + bv.x;
    float xn1 = (xv.y - mean) * rstd * gv.y + bv.y;
    float xn2 = (xv.z - mean) * rstd * gv.z + bv.z;
    float xn3 = (xv.w - mean) * rstd * gv.w + bv.w;
    // w_pot is (D,2) row-major -> interleaved pairs
    float4 p0 = *(const float4*)(wpot + t * 8);
    float4 p1 = *(const float4*)(wpot + t * 8 + 4);
    float a0 = xn0 * p0.x + xn1 * p0.z + xn2 * p1.x + xn3 * p1.z;
    float a1 = xn0 * p0.y + xn1 * p0.w + xn2 * p1.y + xn3 * p1.w;
    float2 pr = blockReduce2(a0, a1);
    if (t == 0) {
        float Vv   = pr.x + bpot[0];
        float praw = pr.y + bpot[1];
        float sp = fmaxf(praw, 0.0f) + log1pf(__expf(-fabsf(praw)));
        g_V[r]     = Vv;
        g_gamma[r] = sp + 0.1f;
    }
}

// ---------------- K2: continued-fraction scans (8 sequential chains) ----------------
__global__ void cf_scan_kernel() {
    int id = blockIdx.x;             // 0..7
    int bb = id & 3;
    const float* Vp = g_V + bb * Nc;
    const float* Gp = g_gamma + bb * Nc;
    if (id < 4) {
        float ar = Vp[0] + 2.0f, ai = -Gp[0];
        g_a[bb * Nc + 0] = make_float2(ar, ai);
        for (int t = 1; t < Nc; t++) {
            float m  = __fdividef(1.0f, ar * ar + ai * ai);
            float dr = Vp[t] + 2.0f, di = -Gp[t];
            float nar = dr - ar * m;
            float nai = di + ai * m;
            ar = nar; ai = nai;
            g_a[bb * Nc + t] = make_float2(ar, ai);
        }
    } else {
        float br = Vp[Nc - 1] + 2.0f, bi = -Gp[Nc - 1];
        g_b[bb * Nc + Nc - 1] = make_float2(br, bi);
        for (int t = Nc - 2; t >= 0; t--) {
            float m  = __fdividef(1.0f, br * br + bi * bi);
            float dr = Vp[t] + 2.0f, di = -Gp[t];
            float nbr = dr - br * m;
            float nbi = di + bi * m;
            br = nbr; bi = nbi;
            g_b[bb * Nc + t] = make_float2(br, bi);
        }
    }
}

// ---------------- K3: G = 1/(a+b-d) -> features ----------------
__global__ void feat_kernel() {
    int i = blockIdx.x * blockDim.x + threadIdx.x;   // 8192 total
    float2 a = g_a[i], b = g_b[i];
    float dr = g_V[i] + 2.0f, di = -g_gamma[i];
    float er = a.x + b.x - dr;
    float ei = a.y + b.y - di;
    float m = __fdividef(1.0f, er * er + ei * ei);
    g_feat[i] = make_float2(er * m, -ei * m);
}

// ---------------- K4: x1 = x + feat@w_bk + b_bk ; LN2 -> g_xn ----------------
__global__ void bk_ln2_kernel(const float* __restrict__ x,
                              const float* __restrict__ wbk, const float* __restrict__ bbk,
                              const float* __restrict__ g2, const float* __restrict__ b2) {
    int r = blockIdx.x, t = threadIdx.x;
    float2 f = g_feat[r];
    const float4 xv = *(const float4*)(x + (size_t)r * Dc + t * 4);
    float4 w0 = *(const float4*)(wbk + t * 4);
    float4 w1 = *(const float4*)(wbk + Dc + t * 4);
    float4 bb = *(const float4*)(bbk + t * 4);
    float4 v;
    v.x = xv.x + f.x * w0.x + f.y * w1.x + bb.x;
    v.y = xv.y + f.x * w0.y + f.y * w1.y + bb.y;
    v.z = xv.z + f.x * w0.z + f.y * w1.z + bb.z;
    v.w = xv.w + f.x * w0.w + f.y * w1.w + bb.w;
    *(float4*)(g_x1 + (size_t)r * Dc + t * 4) = v;
    float s  = v.x + v.y + v.z + v.w;
    float ss = v.x*v.x + v.y*v.y + v.z*v.z + v.w*v.w;
    float2 red = blockReduce2(s, ss);
    float mean = red.x * (1.0f / Dc);
    float var  = red.y * (1.0f / Dc) - mean * mean;
    float rstd = rsqrtf(var + 1e-5f);
    float4 gv = *(const float4*)(g2 + t * 4);
    float4 bv = *(const float4*)(b2 + t * 4);
    float4 o;
    o.x = (v.x - mean) * rstd * gv.x + bv.x;
    o.y = (v.y - mean) * rstd * gv.y + bv.y;
    o.z = (v.z - mean) * rstd * gv.z + bv.z;
    o.w = (v.w - mean) * rstd * gv.w + bv.w;
    *(float4*)(g_xn + (size_t)r * Dc + t * 4) = o;
}

// ---------------- generic LN (for LN3) ----------------
__global__ void ln_kernel(const float* __restrict__ X,
                          const float* __restrict__ g, const float* __restrict__ b,
                          float* __restrict__ out) {
    int r = blockIdx.x, t = threadIdx.x;
    const float4 xv = *(const float4*)(X + (size_t)r * Dc + t * 4);
    float s  = xv.x + xv.y + xv.z + xv.w;
    float ss = xv.x*xv.x + xv.y*xv.y + xv.z*xv.z + xv.w*xv.w;
    float2 red = blockReduce2(s, ss);
    float mean = red.x * (1.0f / Dc);
    float var  = red.y * (1.0f / Dc) - mean * mean;
    float rstd = rsqrtf(var + 1e-5f);
    float4 gv = *(const float4*)(g + t * 4);
    float4 bv = *(const float4*)(b + t * 4);
    float4 o;
    o.x = (xv.x - mean) * rstd * gv.x + bv.x;
    o.y = (xv.y - mean) * rstd * gv.y + bv.y;
    o.z = (xv.z - mean) * rstd * gv.z + bv.z;
    o.w = (xv.w - mean) * rstd * gv.w + bv.w;
    *(float4*)(out + (size_t)r * Dc + t * 4) = o;
}

// ---------------- TF32 tensor-core GEMM ----------------
// C = A(MxK) @ B(KxN) + bias, optional GELU, optional +R.
// Block tile 128x128, BK=16. 8 warps in 4x2; warp tile 32x64 (2x8 m16n8k8 tiles).
template<int ACT, int RES>
__global__ __launch_bounds__(256)
void tf32_gemm_kernel(const float* __restrict__ A, const float* __restrict__ Bm,
                      const float* __restrict__ bias, const float* __restrict__ Rm,
                      float* __restrict__ C, int M, int Nn, int K) {
    __shared__ unsigned As[16][136];   // [k][m], pitch 136 -> conflict-free frag loads
    __shared__ unsigned Bs[16][136];   // [k][n]
    int tid = threadIdx.x;
    int brow = blockIdx.y * 128;
    int bcol = blockIdx.x * 128;
    int wid = tid >> 5, lane = tid & 31;
    int wm = wid & 3, wn = wid >> 2;
    int m_base = wm * 32, n_base = wn * 64;
    int g = lane >> 2, c = lane & 3;

    float acc[2][8][4];
    #pragma unroll
    for (int mt = 0; mt < 2; mt++)
        #pragma unroll
        for (int nt = 0; nt < 8; nt++)
            #pragma unroll
            for (int i = 0; i < 4; i++) acc[mt][nt][i] = 0.0f;

    int ar  = tid >> 1;            // A row within block (0..127)
    int akq = (tid & 1) * 8;       // A k offset (0 or 8)
    int bkr = tid >> 4;            // B k row (0..15)
    int bcq = (tid & 15) * 8;      // B col offset
    const float* aptr = A + (size_t)(brow + ar) * K + akq;
    const float* bptr = Bm + (size_t)bkr * Nn + bcol + bcq;

    for (int k0 = 0; k0 < K; k0 += 16) {
        float4 av0 = *(const float4*)(aptr + k0);
        float4 av1 = *(const float4*)(aptr + k0 + 4);
        float4 bv0 = *(const float4*)(bptr + (size_t)k0 * Nn);
        float4 bv1 = *(const float4*)(bptr + (size_t)k0 * Nn + 4);
        __syncthreads();
        As[akq + 0][ar] = f2tf(av0.x);
        As[akq + 1][ar] = f2tf(av0.y);
        As[akq + 2][ar] = f2tf(av0.z);
        As[akq + 3][ar] = f2tf(av0.w);
        As[akq + 4][ar] = f2tf(av1.x);
        As[akq + 5][ar] = f2tf(av1.y);
        As[akq + 6][ar] = f2tf(av1.z);
        As[akq + 7][ar] = f2tf(av1.w);
        uint4 bs0 = make_uint4(f2tf(bv0.x), f2tf(bv0.y), f2tf(bv0.z), f2tf(bv0.w));
        uint4 bs1 = make_uint4(f2tf(bv1.x), f2tf(bv1.y), f2tf(bv1.z), f2tf(bv1.w));
        *(uint4*)&Bs[bkr][bcq] = bs0;
        *(uint4*)&Bs[bkr][bcq + 4] = bs1;
        __syncthreads();

        #pragma unroll
        for (int kk = 0; kk < 16; kk += 8) {
            unsigned afr[2][4];
            #pragma unroll
            for (int mt = 0; mt < 2; mt++) {
                int mr = m_base + mt * 16 + g;
                afr[mt][0] = As[kk + c][mr];
                afr[mt][1] = As[kk + c][mr + 8];
                afr[mt][2] = As[kk + c + 4][mr];
                afr[mt][3] = As[kk + c + 4][mr + 8];
            }
            unsigned bfr[8][2];
            #pragma unroll
            for (int nt = 0; nt < 8; nt++) {
                int nc = n_base + nt * 8 + g;
                bfr[nt][0] = Bs[kk + c][nc];
                bfr[nt][1] = Bs[kk + c + 4][nc];
            }
            #pragma unroll
            for (int mt = 0; mt < 2; mt++)
                #pragma unroll
                for (int nt = 0; nt < 8; nt++)
                    mma_tf32(acc[mt][nt], afr[mt], bfr[nt]);
        }
    }

    // epilogue
    #pragma unroll
    for (int mt = 0; mt < 2; mt++) {
        #pragma unroll
        for (int nt = 0; nt < 8; nt++) {
            int row0 = brow + m_base + mt * 16 + g;
            int col  = bcol + n_base + nt * 8 + 2 * c;
            float b0 = bias[col], b1 = bias[col + 1];
            #pragma unroll
            for (int h = 0; h < 2; h++) {
                int row = row0 + h * 8;
                float v0 = acc[mt][nt][2 * h]     + b0;
                float v1 = acc[mt][nt][2 * h + 1] + b1;
                if (ACT) { v0 = gelu_tanh(v0); v1 = gelu_tanh(v1); }
                if (RES) {
                    const float2 rv = *(const float2*)(Rm + (size_t)row * Nn + col);
                    v0 += rv.x; v1 += rv.y;
                }
                float2 o = make_float2(v0, v1);
                *(float2*)(C + (size_t)row * Nn + col) = o;
            }
        }
    }
}

// ---------------- Hebbian fast-weight scan ----------------
// grid 128 blocks: (bh = blockIdx.x>>2, colgroup = blockIdx.x&3), 128 threads.
// Each warp owns 4 columns; each lane: 8 rows x 1 column of W in registers.
__global__ void __launch_bounds__(128) hebbian_kernel() {
    int bx = blockIdx.x;
    int bh = bx >> 2, cg = bx & 3;
    int b = bh >> 3, h = bh & 7;
    int tid = threadIdx.x;
    int w = tid >> 5, lane = tid & 31;
    int e  = cg * 16 + w * 4 + (lane & 3);
    int d0 = (lane >> 2) * 8;
    const float* base = g_qkv + (size_t)b * Nc * QKVW;
    const float* gp   = g_gamma + b * Nc;
    float W[8];
    #pragma unroll
    for (int i = 0; i < 8; i++) W[i] = 0.0f;

    const float* qp = base + h * 64 + d0;
    const float* kp = base + 512 + h * 64 + d0;
    const float* vp = base + 1024 + h * 64 + e;
    float4 q0 = *(const float4*)(qp);
    float4 q1 = *(const float4*)(qp + 4);
    float4 k0 = *(const float4*)(kp);
    float4 k1 = *(const float4*)(kp + 4);
    float vv = *vp;
    float* outp = g_heb + (size_t)b * Nc * HEBW + h * 64 + e;

    for (int t = 0; t < Nc; t++) {
        float4 cq0 = q0, cq1 = q1, ck0 = k0, ck1 = k1;
        float cvv = vv;
        float dec = __expf(-gp[t] * 0.01f);
        if (t + 1 < Nc) {  // prefetch next step
            const float* nb = base + (size_t)(t + 1) * QKVW;
            q0 = *(const float4*)(nb + h * 64 + d0);
            q1 = *(const float4*)(nb + h * 64 + d0 + 4);
            k0 = *(const float4*)(nb + 512 + h * 64 + d0);
            k1 = *(const float4*)(nb + 512 + h * 64 + d0 + 4);
            vv = *(nb + 1024 + h * 64 + e);
        }
        float ev = 0.1f * cvv;
        float p = 0.0f;
        W[0] = fmaf(dec, W[0], ck0.x * ev); p = fmaf(cq0.x, W[0], p);
        W[1] = fmaf(dec, W[1], ck0.y * ev); p = fmaf(cq0.y, W[1], p);
        W[2] = fmaf(dec, W[2], ck0.z * ev); p = fmaf(cq0.z, W[2], p);
        W[3] = fmaf(dec, W[3], ck0.w * ev); p = fmaf(cq0.w, W[3], p);
        W[4] = fmaf(dec, W[4], ck1.x * ev); p = fmaf(cq1.x, W[4], p);
        W[5] = fmaf(dec, W[5], ck1.y * ev); p = fmaf(cq1.y, W[5], p);
        W[6] = fmaf(dec, W[6], ck1.z * ev); p = fmaf(cq1.z, W[6], p);
        W[7] = fmaf(dec, W[7], ck1.w * ev); p = fmaf(cq1.w, W[7], p);
        p += __shfl_xor_sync(0xffffffffu, p, 4);
        p += __shfl_xor_sync(0xffffffffu, p, 8);
        p += __shfl_xor_sync(0xffffffffu, p, 16);
        if ((lane >> 2) == 0) outp[(size_t)t * HEBW] = p;
    }
}

// ---------------- host launcher ----------------
extern "C" void kernel_launch(void* const* d_in, const int* in_sizes, int n_in,
                              void* d_out, int out_size) {
    const float* x     = (const float*)d_in[0];
    const float* ln1_g = (const float*)d_in[1];
    const float* ln1_b = (const float*)d_in[2];
    const float* ln2_g = (const float*)d_in[3];
    const float* ln2_b = (const float*)d_in[4];
    const float* ln3_g = (const float*)d_in[5];
    const float* ln3_b = (const float*)d_in[6];
    const float* w_pot = (const float*)d_in[7];
    const float* b_pot = (const float*)d_in[8];
    const float* w_bk  = (const float*)d_in[9];
    const float* b_bk  = (const float*)d_in[10];
    const float* w_qkv = (const float*)d_in[11];
    const float* b_qkv = (const float*)d_in[12];
    const float* w_out = (const float*)d_in[13];
    const float* b_out = (const float*)d_in[14];
    const float* w_ff1 = (const float*)d_in[15];
    const float* b_ff1 = (const float*)d_in[16];
    const float* w_ff2 = (const float*)d_in[17];
    const float* b_ff2 = (const float*)d_in[18];

    float *pX1, *pXN, *pQKV, *pHEB, *pX2, *pFF;
    cudaGetSymbolAddress((void**)&pX1,  g_x1);
    cudaGetSymbolAddress((void**)&pXN,  g_xn);
    cudaGetSymbolAddress((void**)&pQKV, g_qkv);
    cudaGetSymbolAddress((void**)&pHEB, g_heb);
    cudaGetSymbolAddress((void**)&pX2,  g_x2);
    cudaGetSymbolAddress((void**)&pFF,  g_ffbuf);

    // 1. LN1 + potential head
    ln1_pot_kernel<<<ROWS, 256>>>(x, ln1_g, ln1_b, w_pot, b_pot);
    // 2. continued-fraction scans (fwd + bwd, 4 batches each)
    cf_scan_kernel<<<8, 1>>>();
    // 3. Green-function diagonal features
    feat_kernel<<<32, 256>>>();
    // 4. rank-2 injection + LN2
    bk_ln2_kernel<<<ROWS, 256>>>(x, w_bk, b_bk, ln2_g, ln2_b);
    // 5. QKV projection (tensor cores, tf32)
    tf32_gemm_kernel<0, 0><<<dim3(QKVW / 128, ROWS / 128), 256>>>(
        pXN, w_qkv, b_qkv, nullptr, pQKV, ROWS, QKVW, Dc);
    // 6. Hebbian fast-weight scan
    hebbian_kernel<<<128, 128>>>();
    // 7. out-projection + residual(x1)
    tf32_gemm_kernel<0, 1><<<dim3(Dc / 128, ROWS / 128), 256>>>(
        pHEB, w_out, b_out, pX1, pX2, ROWS, Dc, HEBW);
    // 8. LN3
    ln_kernel<<<ROWS, 256>>>(pX2, ln3_g, ln3_b, pXN);
    // 9. FFN up + gelu
    tf32_gemm_kernel<1, 0><<<dim3(FFc / 128, ROWS / 128), 256>>>(
        pXN, w_ff1, b_ff1, nullptr, pFF, ROWS, FFc, Dc);
    // 10. FFN down + residual(x2) -> output
    tf32_gemm_kernel<0, 1><<<dim3(Dc / 128, ROWS / 128), 256>>>(
        pFF, w_ff2, b_ff2, pX2, (float*)d_out, ROWS, Dc, FFc);
}

// round 5
// speedup vs baseline: 1.8132x; 1.0180x over previous
#include <cuda_runtime.h>
#include <math.h>

// Problem constants
#define Bc 4
#define Nc 2048
#define Dc 1024
#define Hc 8
#define HDc 64
#define FFc 4096
#define ROWS (Bc*Nc)            // 8192
#define QKVW (3*Hc*HDc)         // 1536
#define HEBW (Hc*HDc)           // 512

// ---------------- scratch (device globals; no allocs allowed) ----------------
__device__ __align__(16) float  g_V[ROWS];
__device__ __align__(16) float  g_gamma[ROWS];
__device__ __align__(16) float2 g_a[ROWS];
__device__ __align__(16) float2 g_b[ROWS];
__device__ __align__(16) float2 g_feat[ROWS];
__device__ __align__(16) float  g_x1[(size_t)ROWS*Dc];
__device__ __align__(16) float  g_xn[(size_t)ROWS*Dc];
__device__ __align__(16) float  g_qkv[(size_t)ROWS*QKVW];
__device__ __align__(16) float  g_heb[(size_t)ROWS*HEBW];
__device__ __align__(16) float  g_x2[(size_t)ROWS*Dc];
__device__ __align__(16) float  g_ffbuf[(size_t)ROWS*FFc];

// ---------------- helpers ----------------
__device__ __forceinline__ float2 blockReduce2(float a, float b) {
    // blockDim.x == 256
    #pragma unroll
    for (int off = 16; off > 0; off >>= 1) {
        a += __shfl_down_sync(0xffffffffu, a, off);
        b += __shfl_down_sync(0xffffffffu, b, off);
    }
    __shared__ float sa[8], sb[8];
    int w = threadIdx.x >> 5, l = threadIdx.x & 31;
    __syncthreads();
    if (l == 0) { sa[w] = a; sb[w] = b; }
    __syncthreads();
    if (threadIdx.x == 0) {
        float ta = sa[0], tb = sb[0];
        #pragma unroll
        for (int i = 1; i < 8; i++) { ta += sa[i]; tb += sb[i]; }
        sa[0] = ta; sb[0] = tb;
    }
    __syncthreads();
    return make_float2(sa[0], sb[0]);
}

__device__ __forceinline__ float gelu_tanh(float v) {
    const float c = 0.7978845608028654f;
    float t = tanhf(c * (v + 0.044715f * v * v * v));
    return 0.5f * v * (1.0f + t);
}

__device__ __forceinline__ unsigned f2tf(float x) {
    unsigned r;
    asm("cvt.rna.tf32.f32 %0, %1;" : "=r"(r) : "f"(x));
    return r;
}

__device__ __forceinline__ void mma_tf32(float* d, const unsigned* a, const unsigned* b) {
    asm volatile(
        "mma.sync.aligned.m16n8k8.row.col.f32.tf32.tf32.f32 "
        "{%0,%1,%2,%3}, {%4,%5,%6,%7}, {%8,%9}, {%0,%1,%2,%3};"
        : "+f"(d[0]), "+f"(d[1]), "+f"(d[2]), "+f"(d[3])
        : "r"(a[0]), "r"(a[1]), "r"(a[2]), "r"(a[3]), "r"(b[0]), "r"(b[1]));
}

// ---------------- K1: LN1 + potential head -> V, gamma ----------------
__global__ void ln1_pot_kernel(const float* __restrict__ x,
                               const float* __restrict__ g1, const float* __restrict__ b1,
                               const float* __restrict__ wpot, const float* __restrict__ bpot) {
    int r = blockIdx.x, t = threadIdx.x;
    const float4 xv = *(const float4*)(x + (size_t)r * Dc + t * 4);
    float s  = xv.x + xv.y + xv.z + xv.w;
    float ss = xv.x*xv.x + xv.y*xv.y + xv.z*xv.z + xv.w*xv.w;
    float2 red = blockReduce2(s, ss);
    float mean = red.x * (1.0f / Dc);
    float var  = red.y * (1.0f / Dc) - mean * mean;
    float rstd = rsqrtf(var + 1e-5f);
    float4 gv = *(const float4*)(g1 + t * 4);
    float4 bv = *(const float4*)(b1 + t * 4);
    float xn0 = (xv.x - mean) * rstd * gv.x + bv.x;
    float xn1 = (xv.y - mean) * rstd * gv.y + bv.y;
    float xn2 = (xv.z - mean) * rstd * gv.z + bv.z;
    float xn3 = (xv.w - mean) * rstd * gv.w + bv.w;
    // w_pot is (D,2) row-major -> interleaved pairs
    float4 p0 = *(const float4*)(wpot + t * 8);
    float4 p1 = *(const float4*)(wpot + t * 8 + 4);
    float a0 = xn0 * p0.x + xn1 * p0.z + xn2 * p1.x + xn3 * p1.z;
    float a1 = xn0 * p0.y + xn1 * p0.w + xn2 * p1.y + xn3 * p1.w;
    float2 pr = blockReduce2(a0, a1);
    if (t == 0) {
        float Vv   = pr.x + bpot[0];
        float praw = pr.y + bpot[1];
        float sp = fmaxf(praw, 0.0f) + log1pf(__expf(-fabsf(praw)));
        g_V[r]     = Vv;
        g_gamma[r] = sp + 0.1f;
    }
}

// ---------------- K2: continued-fraction scans (8 sequential chains) ----------------
__global__ void cf_scan_kernel() {
    int id = blockIdx.x;             // 0..7
    int bb = id & 3;
    const float* Vp = g_V + bb * Nc;
    const float* Gp = g_gamma + bb * Nc;
    if (id < 4) {
        float ar = Vp[0] + 2.0f, ai = -Gp[0];
        g_a[bb * Nc + 0] = make_float2(ar, ai);
        for (int t = 1; t < Nc; t++) {
            float m  = __fdividef(1.0f, ar * ar + ai * ai);
            float dr = Vp[t] + 2.0f, di = -Gp[t];
            float nar = dr - ar * m;
            float nai = di + ai * m;
            ar = nar; ai = nai;
            g_a[bb * Nc + t] = make_float2(ar, ai);
        }
    } else {
        float br = Vp[Nc - 1] + 2.0f, bi = -Gp[Nc - 1];
        g_b[bb * Nc + Nc - 1] = make_float2(br, bi);
        for (int t = Nc - 2; t >= 0; t--) {
            float m  = __fdividef(1.0f, br * br + bi * bi);
            float dr = Vp[t] + 2.0f, di = -Gp[t];
            float nbr = dr - br * m;
            float nbi = di + bi * m;
            br = nbr; bi = nbi;
            g_b[bb * Nc + t] = make_float2(br, bi);
        }
    }
}

// ---------------- K3: G = 1/(a+b-d) -> features ----------------
__global__ void feat_kernel() {
    int i = blockIdx.x * blockDim.x + threadIdx.x;   // 8192 total
    float2 a = g_a[i], b = g_b[i];
    float dr = g_V[i] + 2.0f, di = -g_gamma[i];
    float er = a.x + b.x - dr;
    float ei = a.y + b.y - di;
    float m = __fdividef(1.0f, er * er + ei * ei);
    g_feat[i] = make_float2(er * m, -ei * m);
}

// ---------------- K4: x1 = x + feat@w_bk + b_bk ; LN2 -> g_xn ----------------
__global__ void bk_ln2_kernel(const float* __restrict__ x,
                              const float* __restrict__ wbk, const float* __restrict__ bbk,
                              const float* __restrict__ g2, const float* __restrict__ b2) {
    int r = blockIdx.x, t = threadIdx.x;
    float2 f = g_feat[r];
    const float4 xv = *(const float4*)(x + (size_t)r * Dc + t * 4);
    float4 w0 = *(const float4*)(wbk + t * 4);
    float4 w1 = *(const float4*)(wbk + Dc + t * 4);
    float4 bb = *(const float4*)(bbk + t * 4);
    float4 v;
    v.x = xv.x + f.x * w0.x + f.y * w1.x + bb.x;
    v.y = xv.y + f.x * w0.y + f.y * w1.y + bb.y;
    v.z = xv.z + f.x * w0.z + f.y * w1.z + bb.z;
    v.w = xv.w + f.x * w0.w + f.y * w1.w + bb.w;
    *(float4*)(g_x1 + (size_t)r * Dc + t * 4) = v;
    float s  = v.x + v.y + v.z + v.w;
    float ss = v.x*v.x + v.y*v.y + v.z*v.z + v.w*v.w;
    float2 red = blockReduce2(s, ss);
    float mean = red.x * (1.0f / Dc);
    float var  = red.y * (1.0f / Dc) - mean * mean;
    float rstd = rsqrtf(var + 1e-5f);
    float4 gv = *(const float4*)(g2 + t * 4);
    float4 bv = *(const float4*)(b2 + t * 4);
    float4 o;
    o.x = (v.x - mean) * rstd * gv.x + bv.x;
    o.y = (v.y - mean) * rstd * gv.y + bv.y;
    o.z = (v.z - mean) * rstd * gv.z + bv.z;
    o.w = (v.w - mean) * rstd * gv.w + bv.w;
    *(float4*)(g_xn + (size_t)r * Dc + t * 4) = o;
}

// ---------------- generic LN (for LN3) ----------------
__global__ void ln_kernel(const float* __restrict__ X,
                          const float* __restrict__ g, const float* __restrict__ b,
                          float* __restrict__ out) {
    int r = blockIdx.x, t = threadIdx.x;
    const float4 xv = *(const float4*)(X + (size_t)r * Dc + t * 4);
    float s  = xv.x + xv.y + xv.z + xv.w;
    float ss = xv.x*xv.x + xv.y*xv.y + xv.z*xv.z + xv.w*xv.w;
    float2 red = blockReduce2(s, ss);
    float mean = red.x * (1.0f / Dc);
    float var  = red.y * (1.0f / Dc) - mean * mean;
    float rstd = rsqrtf(var + 1e-5f);
    float4 gv = *(const float4*)(g + t * 4);
    float4 bv = *(const float4*)(b + t * 4);
    float4 o;
    o.x = (xv.x - mean) * rstd * gv.x + bv.x;
    o.y = (xv.y - mean) * rstd * gv.y + bv.y;
    o.z = (xv.z - mean) * rstd * gv.z + bv.z;
    o.w = (xv.w - mean) * rstd * gv.w + bv.w;
    *(float4*)(out + (size_t)r * Dc + t * 4) = o;
}

// ---------------- TF32 tensor-core GEMM (double-buffered) ----------------
// C = A(MxK) @ B(KxN) + bias, optional GELU, optional +R.
// Block tile 128x128, BK=16, 2-stage smem pipeline + register prefetch.
// 8 warps in 4x2; warp tile 32x64 (2x8 m16n8k8 tiles).
template<int ACT, int RES>
__global__ __launch_bounds__(256)
void tf32_gemm_kernel(const float* __restrict__ A, const float* __restrict__ Bm,
                      const float* __restrict__ bias, const float* __restrict__ Rm,
                      float* __restrict__ C, int M, int Nn, int K) {
    __shared__ unsigned As[2][16][136];   // [stage][k][m]
    __shared__ unsigned Bs[2][16][136];   // [stage][k][n]
    int tid = threadIdx.x;
    int brow = blockIdx.y * 128;
    int bcol = blockIdx.x * 128;
    int wid = tid >> 5, lane = tid & 31;
    int wm = wid & 3, wn = wid >> 2;
    int m_base = wm * 32, n_base = wn * 64;
    int g = lane >> 2, c = lane & 3;

    float acc[2][8][4];
    #pragma unroll
    for (int mt = 0; mt < 2; mt++)
        #pragma unroll
        for (int nt = 0; nt < 8; nt++)
            #pragma unroll
            for (int i = 0; i < 4; i++) acc[mt][nt][i] = 0.0f;

    int ar  = tid >> 1;            // A row within block (0..127)
    int akq = (tid & 1) * 8;       // A k offset (0 or 8)
    int bkr = tid >> 4;            // B k row (0..15)
    int bcq = (tid & 15) * 8;      // B col offset
    const float* aptr = A + (size_t)(brow + ar) * K + akq;
    const float* bptr = Bm + (size_t)bkr * Nn + bcol + bcq;

    // prologue: stage 0 = tile k0=0
    {
        float4 av0 = *(const float4*)(aptr);
        float4 av1 = *(const float4*)(aptr + 4);
        float4 bv0 = *(const float4*)(bptr);
        float4 bv1 = *(const float4*)(bptr + 4);
        As[0][akq + 0][ar] = f2tf(av0.x);
        As[0][akq + 1][ar] = f2tf(av0.y);
        As[0][akq + 2][ar] = f2tf(av0.z);
        As[0][akq + 3][ar] = f2tf(av0.w);
        As[0][akq + 4][ar] = f2tf(av1.x);
        As[0][akq + 5][ar] = f2tf(av1.y);
        As[0][akq + 6][ar] = f2tf(av1.z);
        As[0][akq + 7][ar] = f2tf(av1.w);
        uint4 bs0 = make_uint4(f2tf(bv0.x), f2tf(bv0.y), f2tf(bv0.z), f2tf(bv0.w));
        uint4 bs1 = make_uint4(f2tf(bv1.x), f2tf(bv1.y), f2tf(bv1.z), f2tf(bv1.w));
        *(uint4*)&Bs[0][bkr][bcq] = bs0;
        *(uint4*)&Bs[0][bkr][bcq + 4] = bs1;
    }
    __syncthreads();

    int iters = K >> 4;
    for (int it = 0; it < iters; it++) {
        int cur = it & 1;
        // issue next tile's global loads BEFORE compute so LDG overlaps mma
        float4 av0, av1, bv0, bv1;
        bool has_next = (it + 1 < iters);
        if (has_next) {
            int k0 = (it + 1) << 4;
            av0 = *(const float4*)(aptr + k0);
            av1 = *(const float4*)(aptr + k0 + 4);
            bv0 = *(const float4*)(bptr + (size_t)k0 * Nn);
            bv1 = *(const float4*)(bptr + (size_t)k0 * Nn + 4);
        }

        #pragma unroll
        for (int kk = 0; kk < 16; kk += 8) {
            unsigned afr[2][4];
            #pragma unroll
            for (int mt = 0; mt < 2; mt++) {
                int mr = m_base + mt * 16 + g;
                afr[mt][0] = As[cur][kk + c][mr];
                afr[mt][1] = As[cur][kk + c][mr + 8];
                afr[mt][2] = As[cur][kk + c + 4][mr];
                afr[mt][3] = As[cur][kk + c + 4][mr + 8];
            }
            unsigned bfr[8][2];
            #pragma unroll
            for (int nt = 0; nt < 8; nt++) {
                int nc = n_base + nt * 8 + g;
                bfr[nt][0] = Bs[cur][kk + c][nc];
                bfr[nt][1] = Bs[cur][kk + c + 4][nc];
            }
            #pragma unroll
            for (int mt = 0; mt < 2; mt++)
                #pragma unroll
                for (int nt = 0; nt < 8; nt++)
                    mma_tf32(acc[mt][nt], afr[mt], bfr[nt]);
        }

        if (has_next) {
            int nxt = (it + 1) & 1;
            As[nxt][akq + 0][ar] = f2tf(av0.x);
            As[nxt][akq + 1][ar] = f2tf(av0.y);
            As[nxt][akq + 2][ar] = f2tf(av0.z);
            As[nxt][akq + 3][ar] = f2tf(av0.w);
            As[nxt][akq + 4][ar] = f2tf(av1.x);
            As[nxt][akq + 5][ar] = f2tf(av1.y);
            As[nxt][akq + 6][ar] = f2tf(av1.z);
            As[nxt][akq + 7][ar] = f2tf(av1.w);
            uint4 bs0 = make_uint4(f2tf(bv0.x), f2tf(bv0.y), f2tf(bv0.z), f2tf(bv0.w));
            uint4 bs1 = make_uint4(f2tf(bv1.x), f2tf(bv1.y), f2tf(bv1.z), f2tf(bv1.w));
            *(uint4*)&Bs[nxt][bkr][bcq] = bs0;
            *(uint4*)&Bs[nxt][bkr][bcq + 4] = bs1;
        }
        __syncthreads();
    }

    // epilogue
    #pragma unroll
    for (int mt = 0; mt < 2; mt++) {
        #pragma unroll
        for (int nt = 0; nt < 8; nt++) {
            int row0 = brow + m_base + mt * 16 + g;
            int col  = bcol + n_base + nt * 8 + 2 * c;
            float b0 = bias[col], b1 = bias[col + 1];
            #pragma unroll
            for (int h = 0; h < 2; h++) {
                int row = row0 + h * 8;
                float v0 = acc[mt][nt][2 * h]     + b0;
                float v1 = acc[mt][nt][2 * h + 1] + b1;
                if (ACT) { v0 = gelu_tanh(v0); v1 = gelu_tanh(v1); }
                if (RES) {
                    const float2 rv = *(const float2*)(Rm + (size_t)row * Nn + col);
                    v0 += rv.x; v1 += rv.y;
                }
                float2 o = make_float2(v0, v1);
                *(float2*)(C + (size_t)row * Nn + col) = o;
            }
        }
    }
}

// ---------------- Hebbian fast-weight scan ----------------
// grid 128 blocks: (bh = blockIdx.x>>2, colgroup = blockIdx.x&3), 128 threads.
// Each warp owns 4 columns; each lane: 8 rows x 1 column of W in registers.
__global__ void __launch_bounds__(128) hebbian_kernel() {
    int bx = blockIdx.x;
    int bh = bx >> 2, cg = bx & 3;
    int b = bh >> 3, h = bh & 7;
    int tid = threadIdx.x;
    int w = tid >> 5, lane = tid & 31;
    int e  = cg * 16 + w * 4 + (lane & 3);
    int d0 = (lane >> 2) * 8;
    const float* base = g_qkv + (size_t)b * Nc * QKVW;
    const float* gp   = g_gamma + b * Nc;
    float W[8];
    #pragma unroll
    for (int i = 0; i < 8; i++) W[i] = 0.0f;

    const float* qp = base + h * 64 + d0;
    const float* kp = base + 512 + h * 64 + d0;
    const float* vp = base + 1024 + h * 64 + e;
    float4 q0 = *(const float4*)(qp);
    float4 q1 = *(const float4*)(qp + 4);
    float4 k0 = *(const float4*)(kp);
    float4 k1 = *(const float4*)(kp + 4);
    float vv = *vp;
    float* outp = g_heb + (size_t)b * Nc * HEBW + h * 64 + e;

    for (int t = 0; t < Nc; t++) {
        float4 cq0 = q0, cq1 = q1, ck0 = k0, ck1 = k1;
        float cvv = vv;
        float dec = __expf(-gp[t] * 0.01f);
        if (t + 1 < Nc) {  // prefetch next step
            const float* nb = base + (size_t)(t + 1) * QKVW;
            q0 = *(const float4*)(nb + h * 64 + d0);
            q1 = *(const float4*)(nb + h * 64 + d0 + 4);
            k0 = *(const float4*)(nb + 512 + h * 64 + d0);
            k1 = *(const float4*)(nb + 512 + h * 64 + d0 + 4);
            vv = *(nb + 1024 + h * 64 + e);
        }
        float ev = 0.1f * cvv;
        float p = 0.0f;
        W[0] = fmaf(dec, W[0], ck0.x * ev); p = fmaf(cq0.x, W[0], p);
        W[1] = fmaf(dec, W[1], ck0.y * ev); p = fmaf(cq0.y, W[1], p);
        W[2] = fmaf(dec, W[2], ck0.z * ev); p = fmaf(cq0.z, W[2], p);
        W[3] = fmaf(dec, W[3], ck0.w * ev); p = fmaf(cq0.w, W[3], p);
        W[4] = fmaf(dec, W[4], ck1.x * ev); p = fmaf(cq1.x, W[4], p);
        W[5] = fmaf(dec, W[5], ck1.y * ev); p = fmaf(cq1.y, W[5], p);
        W[6] = fmaf(dec, W[6], ck1.z * ev); p = fmaf(cq1.z, W[6], p);
        W[7] = fmaf(dec, W[7], ck1.w * ev); p = fmaf(cq1.w, W[7], p);
        p += __shfl_xor_sync(0xffffffffu, p, 4);
        p += __shfl_xor_sync(0xffffffffu, p, 8);
        p += __shfl_xor_sync(0xffffffffu, p, 16);
        if ((lane >> 2) == 0) outp[(size_t)t * HEBW] = p;
    }
}

// ---------------- host launcher ----------------
extern "C" void kernel_launch(void* const* d_in, const int* in_sizes, int n_in,
                              void* d_out, int out_size) {
    const float* x     = (const float*)d_in[0];
    const float* ln1_g = (const float*)d_in[1];
    const float* ln1_b = (const float*)d_in[2];
    const float* ln2_g = (const float*)d_in[3];
    const float* ln2_b = (const float*)d_in[4];
    const float* ln3_g = (const float*)d_in[5];
    const float* ln3_b = (const float*)d_in[6];
    const float* w_pot = (const float*)d_in[7];
    const float* b_pot = (const float*)d_in[8];
    const float* w_bk  = (const float*)d_in[9];
    const float* b_bk  = (const float*)d_in[10];
    const float* w_qkv = (const float*)d_in[11];
    const float* b_qkv = (const float*)d_in[12];
    const float* w_out = (const float*)d_in[13];
    const float* b_out = (const float*)d_in[14];
    const float* w_ff1 = (const float*)d_in[15];
    const float* b_ff1 = (const float*)d_in[16];
    const float* w_ff2 = (const float*)d_in[17];
    const float* b_ff2 = (const float*)d_in[18];

    float *pX1, *pXN, *pQKV, *pHEB, *pX2, *pFF;
    cudaGetSymbolAddress((void**)&pX1,  g_x1);
    cudaGetSymbolAddress((void**)&pXN,  g_xn);
    cudaGetSymbolAddress((void**)&pQKV, g_qkv);
    cudaGetSymbolAddress((void**)&pHEB, g_heb);
    cudaGetSymbolAddress((void**)&pX2,  g_x2);
    cudaGetSymbolAddress((void**)&pFF,  g_ffbuf);

    // 1. LN1 + potential head
    ln1_pot_kernel<<<ROWS, 256>>>(x, ln1_g, ln1_b, w_pot, b_pot);
    // 2. continued-fraction scans (fwd + bwd, 4 batches each)
    cf_scan_kernel<<<8, 1>>>();
    // 3. Green-function diagonal features
    feat_kernel<<<32, 256>>>();
    // 4. rank-2 injection + LN2
    bk_ln2_kernel<<<ROWS, 256>>>(x, w_bk, b_bk, ln2_g, ln2_b);
    // 5. QKV projection (tensor cores, tf32)
    tf32_gemm_kernel<0, 0><<<dim3(QKVW / 128, ROWS / 128), 256>>>(
        pXN, w_qkv, b_qkv, nullptr, pQKV, ROWS, QKVW, Dc);
    // 6. Hebbian fast-weight scan
    hebbian_kernel<<<128, 128>>>();
    // 7. out-projection + residual(x1)
    tf32_gemm_kernel<0, 1><<<dim3(Dc / 128, ROWS / 128), 256>>>(
        pHEB, w_out, b_out, pX1, pX2, ROWS, Dc, HEBW);
    // 8. LN3
    ln_kernel<<<ROWS, 256>>>(pX2, ln3_g, ln3_b, pXN);
    // 9. FFN up + gelu
    tf32_gemm_kernel<1, 0><<<dim3(FFc / 128, ROWS / 128), 256>>>(
        pXN, w_ff1, b_ff1, nullptr, pFF, ROWS, FFc, Dc);
    // 10. FFN down + residual(x2) -> output
    tf32_gemm_kernel<0, 1><<<dim3(Dc / 128, ROWS / 128), 256>>>(
        pFF, w_ff2, b_ff2, pX2, (float*)d_out, ROWS, Dc, FFc);
}

// round 11
// speedup vs baseline: 2.3524x; 1.2974x over previous
#include <cuda_runtime.h>
#include <cuda_fp16.h>
#include <math.h>

// Problem constants
#define Bc 4
#define Nc 2048
#define Dc 1024
#define Hc 8
#define HDc 64
#define FFc 4096
#define ROWS (Bc*Nc)            // 8192
#define QKVW (3*Hc*HDc)         // 1536
#define HEBW (Hc*HDc)           // 512

// ---------------- scratch (device globals; no allocs allowed) ----------------
__device__ __align__(16) float  g_V[ROWS];
__device__ __align__(16) float  g_gamma[ROWS];
__device__ __align__(16) float2 g_a[ROWS];
__device__ __align__(16) float2 g_b[ROWS];
__device__ __align__(16) float2 g_feat[ROWS];
__device__ __align__(16) float  g_x1[(size_t)ROWS*Dc];
__device__ __align__(16) float  g_xn[(size_t)ROWS*Dc];
__device__ __align__(16) float  g_qkv[(size_t)ROWS*QKVW];
__device__ __align__(16) float  g_heb[(size_t)ROWS*HEBW];
__device__ __align__(16) float  g_x2[(size_t)ROWS*Dc];
__device__ __align__(16) float  g_ffbuf[(size_t)ROWS*FFc];

// ---------------- helpers ----------------
__device__ __forceinline__ float2 blockReduce2(float a, float b) {
    // blockDim.x == 256
    #pragma unroll
    for (int off = 16; off > 0; off >>= 1) {
        a += __shfl_down_sync(0xffffffffu, a, off);
        b += __shfl_down_sync(0xffffffffu, b, off);
    }
    __shared__ float sa[8], sb[8];
    int w = threadIdx.x >> 5, l = threadIdx.x & 31;
    __syncthreads();
    if (l == 0) { sa[w] = a; sb[w] = b; }
    __syncthreads();
    if (threadIdx.x == 0) {
        float ta = sa[0], tb = sb[0];
        #pragma unroll
        for (int i = 1; i < 8; i++) { ta += sa[i]; tb += sb[i]; }
        sa[0] = ta; sb[0] = tb;
    }
    __syncthreads();
    return make_float2(sa[0], sb[0]);
}

__device__ __forceinline__ float gelu_tanh(float v) {
    const float c = 0.7978845608028654f;
    float t = tanhf(c * (v + 0.044715f * v * v * v));
    return 0.5f * v * (1.0f + t);
}

__device__ __forceinline__ unsigned pack_h2(float lo, float hi) {
    __half2 h = __floats2half2_rn(lo, hi);   // .x = lo (low half), .y = hi
    return *reinterpret_cast<unsigned*>(&h);
}

__device__ __forceinline__ void mma_f16(float* d, const unsigned* a, const unsigned* b) {
    asm volatile(
        "mma.sync.aligned.m16n8k16.row.col.f32.f16.f16.f32 "
        "{%0,%1,%2,%3}, {%4,%5,%6,%7}, {%8,%9}, {%0,%1,%2,%3};"
        : "+f"(d[0]), "+f"(d[1]), "+f"(d[2]), "+f"(d[3])
        : "r"(a[0]), "r"(a[1]), "r"(a[2]), "r"(a[3]), "r"(b[0]), "r"(b[1]));
}

// ---------------- K1: LN1 + potential head -> V, gamma ----------------
__global__ void ln1_pot_kernel(const float* __restrict__ x,
                               const float* __restrict__ g1, const float* __restrict__ b1,
                               const float* __restrict__ wpot, const float* __restrict__ bpot) {
    int r = blockIdx.x, t = threadIdx.x;
    const float4 xv = *(const float4*)(x + (size_t)r * Dc + t * 4);
    float s  = xv.x + xv.y + xv.z + xv.w;
    float ss = xv.x*xv.x + xv.y*xv.y + xv.z*xv.z + xv.w*xv.w;
    float2 red = blockReduce2(s, ss);
    float mean = red.x * (1.0f / Dc);
    float var  = red.y * (1.0f / Dc) - mean * mean;
    float rstd = rsqrtf(var + 1e-5f);
    float4 gv = *(const float4*)(g1 + t * 4);
    float4 bv = *(const float4*)(b1 + t * 4);
    float xn0 = (xv.x - mean) * rstd * gv.x + bv.x;
    float xn1 = (xv.y - mean) * rstd * gv.y + bv.y;
    float xn2 = (xv.z - mean) * rstd * gv.z + bv.z;
    float xn3 = (xv.w - mean) * rstd * gv.w + bv.w;
    // w_pot is (D,2) row-major -> interleaved pairs
    float4 p0 = *(const float4*)(wpot + t * 8);
    float4 p1 = *(const float4*)(wpot + t * 8 + 4);
    float a0 = xn0 * p0.x + xn1 * p0.z + xn2 * p1.x + xn3 * p1.z;
    float a1 = xn0 * p0.y + xn1 * p0.w + xn2 * p1.y + xn3 * p1.w;
    float2 pr = blockReduce2(a0, a1);
    if (t == 0) {
        float Vv   = pr.x + bpot[0];
        float praw = pr.y + bpot[1];
        float sp = fmaxf(praw, 0.0f) + log1pf(__expf(-fabsf(praw)));
        g_V[r]     = Vv;
        g_gamma[r] = sp + 0.1f;
    }
}

// ---------------- K2: continued-fraction scans (8 sequential chains) ----------------
__global__ void cf_scan_kernel() {
    int id = blockIdx.x;             // 0..7
    int bb = id & 3;
    const float* Vp = g_V + bb * Nc;
    const float* Gp = g_gamma + bb * Nc;
    if (id < 4) {
        float ar = Vp[0] + 2.0f, ai = -Gp[0];
        g_a[bb * Nc + 0] = make_float2(ar, ai);
        for (int t = 1; t < Nc; t++) {
            float m  = __fdividef(1.0f, ar * ar + ai * ai);
            float dr = Vp[t] + 2.0f, di = -Gp[t];
            float nar = dr - ar * m;
            float nai = di + ai * m;
            ar = nar; ai = nai;
            g_a[bb * Nc + t] = make_float2(ar, ai);
        }
    } else {
        float br = Vp[Nc - 1] + 2.0f, bi = -Gp[Nc - 1];
        g_b[bb * Nc + Nc - 1] = make_float2(br, bi);
        for (int t = Nc - 2; t >= 0; t--) {
            float m  = __fdividef(1.0f, br * br + bi * bi);
            float dr = Vp[t] + 2.0f, di = -Gp[t];
            float nbr = dr - br * m;
            float nbi = di + bi * m;
            br = nbr; bi = nbi;
            g_b[bb * Nc + t] = make_float2(br, bi);
        }
    }
}

// ---------------- K3: G = 1/(a+b-d) -> features ----------------
__global__ void feat_kernel() {
    int i = blockIdx.x * blockDim.x + threadIdx.x;   // 8192 total
    float2 a = g_a[i], b = g_b[i];
    float dr = g_V[i] + 2.0f, di = -g_gamma[i];
    float er = a.x + b.x - dr;
    float ei = a.y + b.y - di;
    float m = __fdividef(1.0f, er * er + ei * ei);
    g_feat[i] = make_float2(er * m, -ei * m);
}

// ---------------- K4: x1 = x + feat@w_bk + b_bk ; LN2 -> g_xn ----------------
__global__ void bk_ln2_kernel(const float* __restrict__ x,
                              const float* __restrict__ wbk, const float* __restrict__ bbk,
                              const float* __restrict__ g2, const float* __restrict__ b2) {
    int r = blockIdx.x, t = threadIdx.x;
    float2 f = g_feat[r];
    const float4 xv = *(const float4*)(x + (size_t)r * Dc + t * 4);
    float4 w0 = *(const float4*)(wbk + t * 4);
    float4 w1 = *(const float4*)(wbk + Dc + t * 4);
    float4 bb = *(const float4*)(bbk + t * 4);
    float4 v;
    v.x = xv.x + f.x * w0.x + f.y * w1.x + bb.x;
    v.y = xv.y + f.x * w0.y + f.y * w1.y + bb.y;
    v.z = xv.z + f.x * w0.z + f.y * w1.z + bb.z;
    v.w = xv.w + f.x * w0.w + f.y * w1.w + bb.w;
    *(float4*)(g_x1 + (size_t)r * Dc + t * 4) = v;
    float s  = v.x + v.y + v.z + v.w;
    float ss = v.x*v.x + v.y*v.y + v.z*v.z + v.w*v.w;
    float2 red = blockReduce2(s, ss);
    float mean = red.x * (1.0f / Dc);
    float var  = red.y * (1.0f / Dc) - mean * mean;
    float rstd = rsqrtf(var + 1e-5f);
    float4 gv = *(const float4*)(g2 + t * 4);
    float4 bv = *(const float4*)(b2 + t * 4);
    float4 o;
    o.x = (v.x - mean) * rstd * gv.x + bv.x;
    o.y = (v.y - mean) * rstd * gv.y + bv.y;
    o.z = (v.z - mean) * rstd * gv.z + bv.z;
    o.w = (v.w - mean) * rstd * gv.w + bv.w;
    *(float4*)(g_xn + (size_t)r * Dc + t * 4) = o;
}

// ---------------- generic LN (for LN3) ----------------
__global__ void ln_kernel(const float* __restrict__ X,
                          const float* __restrict__ g, const float* __restrict__ b,
                          float* __restrict__ out) {
    int r = blockIdx.x, t = threadIdx.x;
    const float4 xv = *(const float4*)(X + (size_t)r * Dc + t * 4);
    float s  = xv.x + xv.y + xv.z + xv.w;
    float ss = xv.x*xv.x + xv.y*xv.y + xv.z*xv.z + xv.w*xv.w;
    float2 red = blockReduce2(s, ss);
    float mean = red.x * (1.0f / Dc);
    float var  = red.y * (1.0f / Dc) - mean * mean;
    float rstd = rsqrtf(var + 1e-5f);
    float4 gv = *(const float4*)(g + t * 4);
    float4 bv = *(const float4*)(b + t * 4);
    float4 o;
    o.x = (xv.x - mean) * rstd * gv.x + bv.x;
    o.y = (xv.y - mean) * rstd * gv.y + bv.y;
    o.z = (xv.z - mean) * rstd * gv.z + bv.z;
    o.w = (xv.w - mean) * rstd * gv.w + bv.w;
    *(float4*)(out + (size_t)r * Dc + t * 4) = o;
}

// ---------------- FP16 tensor-core GEMM (double-buffered, m16n8k16) ----------------
// C = A(MxK) @ B(KxN) + bias, optional GELU, optional +R.
// Block tile 128x128, BK=16, 2-stage smem pipeline + register prefetch.
// 8 warps in 4x2; warp tile 32x64 (2x8 m16n8k16 tiles, ONE k-step per BK tile).
// Smem holds half2 pairs along k: As2[k2][m], Bs2[k2][n], k2 = k/2 in 0..7.
template<int ACT, int RES>
__global__ __launch_bounds__(256)
void h16_gemm_kernel(const float* __restrict__ A, const float* __restrict__ Bm,
                     const float* __restrict__ bias, const float* __restrict__ Rm,
                     float* __restrict__ C, int M, int Nn, int K) {
    __shared__ unsigned As2[2][8][136];   // [stage][k2][m]  (half2: lo=even k, hi=odd k)
    __shared__ unsigned Bs2[2][8][136];   // [stage][k2][n]
    int tid = threadIdx.x;
    int brow = blockIdx.y * 128;
    int bcol = blockIdx.x * 128;
    int wid = tid >> 5, lane = tid & 31;
    int wm = wid & 3, wn = wid >> 2;
    int m_base = wm * 32, n_base = wn * 64;
    int g = lane >> 2, c = lane & 3;

    float acc[2][8][4];
    #pragma unroll
    for (int mt = 0; mt < 2; mt++)
        #pragma unroll
        for (int nt = 0; nt < 8; nt++)
            #pragma unroll
            for (int i = 0; i < 4; i++) acc[mt][nt][i] = 0.0f;

    // A loads: thread -> row ar (0..127), k range akq..akq+7
    int ar  = tid >> 1;
    int akq = (tid & 1) * 8;
    const float* aptr = A + (size_t)(brow + ar) * K + akq;
    // B loads: thread -> k-pair bk2 (0..7), 4 n cols at bn
    int bk2 = tid >> 5;              // 0..7
    int bn  = (tid & 31) * 4;        // 0..124
    const float* bptr = Bm + (size_t)(2 * bk2) * Nn + bcol + bn;

    // prologue: stage 0 = tile k0=0
    {
        float4 av0 = *(const float4*)(aptr);
        float4 av1 = *(const float4*)(aptr + 4);
        int k2b = akq >> 1;
        As2[0][k2b + 0][ar] = pack_h2(av0.x, av0.y);
        As2[0][k2b + 1][ar] = pack_h2(av0.z, av0.w);
        As2[0][k2b + 2][ar] = pack_h2(av1.x, av1.y);
        As2[0][k2b + 3][ar] = pack_h2(av1.z, av1.w);
        float4 bv0 = *(const float4*)(bptr);
        float4 bv1 = *(const float4*)(bptr + Nn);
        uint4 bs = make_uint4(pack_h2(bv0.x, bv1.x), pack_h2(bv0.y, bv1.y),
                              pack_h2(bv0.z, bv1.z), pack_h2(bv0.w, bv1.w));
        *(uint4*)&Bs2[0][bk2][bn] = bs;
    }
    __syncthreads();

    int iters = K >> 4;
    for (int it = 0; it < iters; it++) {
        int cur = it & 1;
        bool has_next = (it + 1 < iters);
        // issue next tile's global loads BEFORE compute so LDG overlaps mma
        float4 av0, av1, bv0, bv1;
        if (has_next) {
            int k0 = (it + 1) << 4;
            av0 = *(const float4*)(aptr + k0);
            av1 = *(const float4*)(aptr + k0 + 4);
            bv0 = *(const float4*)(bptr + (size_t)k0 * Nn);
            bv1 = *(const float4*)(bptr + (size_t)(k0 + 1) * Nn);
        }

        // one m16n8k16 k-step covers the whole BK=16 tile
        unsigned afr[2][4];
        #pragma unroll
        for (int mt = 0; mt < 2; mt++) {
            int mr = m_base + mt * 16 + g;
            afr[mt][0] = As2[cur][c][mr];
            afr[mt][1] = As2[cur][c][mr + 8];
            afr[mt][2] = As2[cur][c + 4][mr];
            afr[mt][3] = As2[cur][c + 4][mr + 8];
        }
        unsigned bfr[8][2];
        #pragma unroll
        for (int nt = 0; nt < 8; nt++) {
            int nc = n_base + nt * 8 + g;
            bfr[nt][0] = Bs2[cur][c][nc];
            bfr[nt][1] = Bs2[cur][c + 4][nc];
        }
        #pragma unroll
        for (int mt = 0; mt < 2; mt++)
            #pragma unroll
            for (int nt = 0; nt < 8; nt++)
                mma_f16(acc[mt][nt], afr[mt], bfr[nt]);

        if (has_next) {
            int nxt = (it + 1) & 1;
            int k2b = akq >> 1;
            As2[nxt][k2b + 0][ar] = pack_h2(av0.x, av0.y);
            As2[nxt][k2b + 1][ar] = pack_h2(av0.z, av0.w);
            As2[nxt][k2b + 2][ar] = pack_h2(av1.x, av1.y);
            As2[nxt][k2b + 3][ar] = pack_h2(av1.z, av1.w);
            uint4 bs = make_uint4(pack_h2(bv0.x, bv1.x), pack_h2(bv0.y, bv1.y),
                                  pack_h2(bv0.z, bv1.z), pack_h2(bv0.w, bv1.w));
            *(uint4*)&Bs2[nxt][bk2][bn] = bs;
        }
        __syncthreads();
    }

    // epilogue
    #pragma unroll
    for (int mt = 0; mt < 2; mt++) {
        #pragma unroll
        for (int nt = 0; nt < 8; nt++) {
            int row0 = brow + m_base + mt * 16 + g;
            int col  = bcol + n_base + nt * 8 + 2 * c;
            float b0 = bias[col], b1 = bias[col + 1];
            #pragma unroll
            for (int h = 0; h < 2; h++) {
                int row = row0 + h * 8;
                float v0 = acc[mt][nt][2 * h]     + b0;
                float v1 = acc[mt][nt][2 * h + 1] + b1;
                if (ACT) { v0 = gelu_tanh(v0); v1 = gelu_tanh(v1); }
                if (RES) {
                    const float2 rv = *(const float2*)(Rm + (size_t)row * Nn + col);
                    v0 += rv.x; v1 += rv.y;
                }
                float2 o = make_float2(v0, v1);
                *(float2*)(C + (size_t)row * Nn + col) = o;
            }
        }
    }
}

// ---------------- Hebbian fast-weight scan ----------------
// grid 128 blocks: (bh = blockIdx.x>>2, colgroup = blockIdx.x&3), 128 threads.
// Each warp owns 4 columns; each lane: 8 rows x 1 column of W in registers.
__global__ void __launch_bounds__(128) hebbian_kernel() {
    int bx = blockIdx.x;
    int bh = bx >> 2, cg = bx & 3;
    int b = bh >> 3, h = bh & 7;
    int tid = threadIdx.x;
    int w = tid >> 5, lane = tid & 31;
    int e  = cg * 16 + w * 4 + (lane & 3);
    int d0 = (lane >> 2) * 8;
    const float* base = g_qkv + (size_t)b * Nc * QKVW;
    const float* gp   = g_gamma + b * Nc;
    float W[8];
    #pragma unroll
    for (int i = 0; i < 8; i++) W[i] = 0.0f;

    const float* qp = base + h * 64 + d0;
    const float* kp = base + 512 + h * 64 + d0;
    const float* vp = base + 1024 + h * 64 + e;
    float4 q0 = *(const float4*)(qp);
    float4 q1 = *(const float4*)(qp + 4);
    float4 k0 = *(const float4*)(kp);
    float4 k1 = *(const float4*)(kp + 4);
    float vv = *vp;
    float* outp = g_heb + (size_t)b * Nc * HEBW + h * 64 + e;

    for (int t = 0; t < Nc; t++) {
        float4 cq0 = q0, cq1 = q1, ck0 = k0, ck1 = k1;
        float cvv = vv;
        float dec = __expf(-gp[t] * 0.01f);
        if (t + 1 < Nc) {  // prefetch next step
            const float* nb = base + (size_t)(t + 1) * QKVW;
            q0 = *(const float4*)(nb + h * 64 + d0);
            q1 = *(const float4*)(nb + h * 64 + d0 + 4);
            k0 = *(const float4*)(nb + 512 + h * 64 + d0);
            k1 = *(const float4*)(nb + 512 + h * 64 + d0 + 4);
            vv = *(nb + 1024 + h * 64 + e);
        }
        float ev = 0.1f * cvv;
        float p = 0.0f;
        W[0] = fmaf(dec, W[0], ck0.x * ev); p = fmaf(cq0.x, W[0], p);
        W[1] = fmaf(dec, W[1], ck0.y * ev); p = fmaf(cq0.y, W[1], p);
        W[2] = fmaf(dec, W[2], ck0.z * ev); p = fmaf(cq0.z, W[2], p);
        W[3] = fmaf(dec, W[3], ck0.w * ev); p = fmaf(cq0.w, W[3], p);
        W[4] = fmaf(dec, W[4], ck1.x * ev); p = fmaf(cq1.x, W[4], p);
        W[5] = fmaf(dec, W[5], ck1.y * ev); p = fmaf(cq1.y, W[5], p);
        W[6] = fmaf(dec, W[6], ck1.z * ev); p = fmaf(cq1.z, W[6], p);
        W[7] = fmaf(dec, W[7], ck1.w * ev); p = fmaf(cq1.w, W[7], p);
        p += __shfl_xor_sync(0xffffffffu, p, 4);
        p += __shfl_xor_sync(0xffffffffu, p, 8);
        p += __shfl_xor_sync(0xffffffffu, p, 16);
        if ((lane >> 2) == 0) outp[(size_t)t * HEBW] = p;
    }
}

// ---------------- host launcher ----------------
extern "C" void kernel_launch(void* const* d_in, const int* in_sizes, int n_in,
                              void* d_out, int out_size) {
    const float* x     = (const float*)d_in[0];
    const float* ln1_g = (const float*)d_in[1];
    const float* ln1_b = (const float*)d_in[2];
    const float* ln2_g = (const float*)d_in[3];
    const float* ln2_b = (const float*)d_in[4];
    const float* ln3_g = (const float*)d_in[5];
    const float* ln3_b = (const float*)d_in[6];
    const float* w_pot = (const float*)d_in[7];
    const float* b_pot = (const float*)d_in[8];
    const float* w_bk  = (const float*)d_in[9];
    const float* b_bk  = (const float*)d_in[10];
    const float* w_qkv = (const float*)d_in[11];
    const float* b_qkv = (const float*)d_in[12];
    const float* w_out = (const float*)d_in[13];
    const float* b_out = (const float*)d_in[14];
    const float* w_ff1 = (const float*)d_in[15];
    const float* b_ff1 = (const float*)d_in[16];
    const float* w_ff2 = (const float*)d_in[17];
    const float* b_ff2 = (const float*)d_in[18];

    float *pX1, *pXN, *pQKV, *pHEB, *pX2, *pFF;
    cudaGetSymbolAddress((void**)&pX1,  g_x1);
    cudaGetSymbolAddress((void**)&pXN,  g_xn);
    cudaGetSymbolAddress((void**)&pQKV, g_qkv);
    cudaGetSymbolAddress((void**)&pHEB, g_heb);
    cudaGetSymbolAddress((void**)&pX2,  g_x2);
    cudaGetSymbolAddress((void**)&pFF,  g_ffbuf);

    // 1. LN1 + potential head
    ln1_pot_kernel<<<ROWS, 256>>>(x, ln1_g, ln1_b, w_pot, b_pot);
    // 2. continued-fraction scans (fwd + bwd, 4 batches each)
    cf_scan_kernel<<<8, 1>>>();
    // 3. Green-function diagonal features
    feat_kernel<<<32, 256>>>();
    // 4. rank-2 injection + LN2
    bk_ln2_kernel<<<ROWS, 256>>>(x, w_bk, b_bk, ln2_g, ln2_b);
    // 5. QKV projection (fp16 tensor cores)
    h16_gemm_kernel<0, 0><<<dim3(QKVW / 128, ROWS / 128), 256>>>(
        pXN, w_qkv, b_qkv, nullptr, pQKV, ROWS, QKVW, Dc);
    // 6. Hebbian fast-weight scan
    hebbian_kernel<<<128, 128>>>();
    // 7. out-projection + residual(x1)
    h16_gemm_kernel<0, 1><<<dim3(Dc / 128, ROWS / 128), 256>>>(
        pHEB, w_out, b_out, pX1, pX2, ROWS, Dc, HEBW);
    // 8. LN3
    ln_kernel<<<ROWS, 256>>>(pX2, ln3_g, ln3_b, pXN);
    // 9. FFN up + gelu
    h16_gemm_kernel<1, 0><<<dim3(FFc / 128, ROWS / 128), 256>>>(
        pXN, w_ff1, b_ff1, nullptr, pFF, ROWS, FFc, Dc);
    // 10. FFN down + residual(x2) -> output
    h16_gemm_kernel<0, 1><<<dim3(Dc / 128, ROWS / 128), 256>>>(
        pFF, w_ff2, b_ff2, pX2, (float*)d_out, ROWS, Dc, FFc);
}

// round 15
// speedup vs baseline: 3.0227x; 1.2849x over previous
#include <cuda_runtime.h>
#include <cuda_fp16.h>
#include <math.h>

// Problem constants
#define Bc 4
#define Nc 2048
#define Dc 1024
#define Hc 8
#define HDc 64
#define FFc 4096
#define ROWS (Bc*Nc)            // 8192
#define QKVW (3*Hc*HDc)         // 1536
#define HEBW (Hc*HDc)           // 512

// ---------------- scratch (device globals; no allocs allowed) ----------------
__device__ __align__(16) float  g_V[ROWS];
__device__ __align__(16) float  g_gamma[ROWS];
__device__ __align__(16) float  g_decay[ROWS];
__device__ __align__(16) float2 g_a[ROWS];
__device__ __align__(16) float2 g_b[ROWS];
__device__ __align__(16) float2 g_feat[ROWS];
__device__ __align__(16) float  g_x1[(size_t)ROWS*Dc];
__device__ __align__(16) float  g_xn[(size_t)ROWS*Dc];
__device__ __align__(16) float  g_qkv[(size_t)ROWS*QKVW];
__device__ __align__(16) float  g_heb[(size_t)ROWS*HEBW];
__device__ __align__(16) float  g_x2[(size_t)ROWS*Dc];
__device__ __align__(16) float  g_ffbuf[(size_t)ROWS*FFc];

// ---------------- helpers ----------------
__device__ __forceinline__ float2 blockReduce2(float a, float b) {
    // blockDim.x == 256
    #pragma unroll
    for (int off = 16; off > 0; off >>= 1) {
        a += __shfl_down_sync(0xffffffffu, a, off);
        b += __shfl_down_sync(0xffffffffu, b, off);
    }
    __shared__ float sa[8], sb[8];
    int w = threadIdx.x >> 5, l = threadIdx.x & 31;
    __syncthreads();
    if (l == 0) { sa[w] = a; sb[w] = b; }
    __syncthreads();
    if (threadIdx.x == 0) {
        float ta = sa[0], tb = sb[0];
        #pragma unroll
        for (int i = 1; i < 8; i++) { ta += sa[i]; tb += sb[i]; }
        sa[0] = ta; sb[0] = tb;
    }
    __syncthreads();
    return make_float2(sa[0], sb[0]);
}

__device__ __forceinline__ float gelu_tanh(float v) {
    const float c = 0.7978845608028654f;
    float t = tanhf(c * (v + 0.044715f * v * v * v));
    return 0.5f * v * (1.0f + t);
}

__device__ __forceinline__ unsigned pack_h2(float lo, float hi) {
    __half2 h = __floats2half2_rn(lo, hi);   // .x = lo (low half), .y = hi
    return *reinterpret_cast<unsigned*>(&h);
}

__device__ __forceinline__ void mma_f16(float* d, const unsigned* a, const unsigned* b) {
    asm volatile(
        "mma.sync.aligned.m16n8k16.row.col.f32.f16.f16.f32 "
        "{%0,%1,%2,%3}, {%4,%5,%6,%7}, {%8,%9}, {%0,%1,%2,%3};"
        : "+f"(d[0]), "+f"(d[1]), "+f"(d[2]), "+f"(d[3])
        : "r"(a[0]), "r"(a[1]), "r"(a[2]), "r"(a[3]), "r"(b[0]), "r"(b[1]));
}

// complex helpers
__device__ __forceinline__ float2 cmul(float2 a, float2 b) {
    return make_float2(a.x*b.x - a.y*b.y, a.x*b.y + a.y*b.x);
}
__device__ __forceinline__ float2 cadd(float2 a, float2 b) {
    return make_float2(a.x+b.x, a.y+b.y);
}
__device__ __forceinline__ float2 csub(float2 a, float2 b) {
    return make_float2(a.x-b.x, a.y-b.y);
}

// ---------------- K1: LN1 + potential head -> V, gamma ----------------
__global__ void ln1_pot_kernel(const float* __restrict__ x,
                               const float* __restrict__ g1, const float* __restrict__ b1,
                               const float* __restrict__ wpot, const float* __restrict__ bpot) {
    int r = blockIdx.x, t = threadIdx.x;
    const float4 xv = *(const float4*)(x + (size_t)r * Dc + t * 4);
    float s  = xv.x + xv.y + xv.z + xv.w;
    float ss = xv.x*xv.x + xv.y*xv.y + xv.z*xv.z + xv.w*xv.w;
    float2 red = blockReduce2(s, ss);
    float mean = red.x * (1.0f / Dc);
    float var  = red.y * (1.0f / Dc) - mean * mean;
    float rstd = rsqrtf(var + 1e-5f);
    float4 gv = *(const float4*)(g1 + t * 4);
    float4 bv = *(const float4*)(b1 + t * 4);
    float xn0 = (xv.x - mean) * rstd * gv.x + bv.x;
    float xn1 = (xv.y - mean) * rstd * gv.y + bv.y;
    float xn2 = (xv.z - mean) * rstd * gv.z + bv.z;
    float xn3 = (xv.w - mean) * rstd * gv.w + bv.w;
    // w_pot is (D,2) row-major -> interleaved pairs
    float4 p0 = *(const float4*)(wpot + t * 8);
    float4 p1 = *(const float4*)(wpot + t * 8 + 4);
    float a0 = xn0 * p0.x + xn1 * p0.z + xn2 * p1.x + xn3 * p1.z;
    float a1 = xn0 * p0.y + xn1 * p0.w + xn2 * p1.y + xn3 * p1.w;
    float2 pr = blockReduce2(a0, a1);
    if (t == 0) {
        float Vv   = pr.x + bpot[0];
        float praw = pr.y + bpot[1];
        float sp = fmaxf(praw, 0.0f) + log1pf(__expf(-fabsf(praw)));
        g_V[r]     = Vv;
        g_gamma[r] = sp + 0.1f;
    }
}

// ---------------- K2: continued-fraction scans (parallel Mobius scan) ----------------
// a_i = d_i - 1/a_{i-1}  ==  Mobius transform of M_i = [[d_i,-1],[1,0]].
// One 256-thread block per chain (4 fwd + 4 bwd). Each thread: serial product of
// its 8 M's, Hillis-Steele smem scan over 2x2 complex matrices with max-norm
// renormalization (Mobius is scale-invariant), then stable scalar re-walk.
__global__ void __launch_bounds__(256) cf_scan_par_kernel() {
    __shared__ float2 S[256][4];
    int blk = blockIdx.x;            // 0..7
    int bb  = blk & 3;
    int dirb = blk >> 2;             // 0 fwd, 1 bwd
    int t = threadIdx.x;
    const float* Vp = g_V + bb * Nc;
    const float* Gp = g_gamma + bb * Nc;

    // local product over this thread's 8 elements (skip element 0: M_0 = I)
    float2 La = make_float2(1.f, 0.f), Lb = make_float2(0.f, 0.f);
    float2 Lc = make_float2(0.f, 0.f), Ld = make_float2(1.f, 0.f);
    #pragma unroll
    for (int j = 0; j < 8; j++) {
        int idx = t * 8 + j;
        if (idx == 0) continue;
        int i = dirb ? (Nc - 1 - idx) : idx;
        float2 dd = make_float2(Vp[i] + 2.0f, -Gp[i]);
        float2 na = csub(cmul(dd, La), Lc);
        float2 nb = csub(cmul(dd, Lb), Ld);
        Lc = La; Ld = Lb; La = na; Lb = nb;
    }
    {   // normalize
        float nm = fmaxf(fmaxf(fabsf(La.x)+fabsf(La.y), fabsf(Lb.x)+fabsf(Lb.y)),
                         fmaxf(fabsf(Lc.x)+fabsf(Lc.y), fabsf(Ld.x)+fabsf(Ld.y)));
        float iv = __fdividef(1.0f, fmaxf(nm, 1e-30f));
        La.x*=iv; La.y*=iv; Lb.x*=iv; Lb.y*=iv; Lc.x*=iv; Lc.y*=iv; Ld.x*=iv; Ld.y*=iv;
    }
    S[t][0]=La; S[t][1]=Lb; S[t][2]=Lc; S[t][3]=Ld;

    // inclusive scan: cur = cur * prev
    for (int off = 1; off < 256; off <<= 1) {
        __syncthreads();
        float2 Pa, Pb, Pc, Pd;
        bool has = (t >= off);
        if (has) { Pa=S[t-off][0]; Pb=S[t-off][1]; Pc=S[t-off][2]; Pd=S[t-off][3]; }
        __syncthreads();
        if (has) {
            float2 na = cadd(cmul(La,Pa), cmul(Lb,Pc));
            float2 nb = cadd(cmul(La,Pb), cmul(Lb,Pd));
            float2 nc = cadd(cmul(Lc,Pa), cmul(Ld,Pc));
            float2 nd = cadd(cmul(Lc,Pb), cmul(Ld,Pd));
            La=na; Lb=nb; Lc=nc; Ld=nd;
            float nm = fmaxf(fmaxf(fabsf(La.x)+fabsf(La.y), fabsf(Lb.x)+fabsf(Lb.y)),
                             fmaxf(fabsf(Lc.x)+fabsf(Lc.y), fabsf(Ld.x)+fabsf(Ld.y)));
            float iv = __fdividef(1.0f, fmaxf(nm, 1e-30f));
            La.x*=iv; La.y*=iv; Lb.x*=iv; Lb.y*=iv; Lc.x*=iv; Lc.y*=iv; Ld.x*=iv; Ld.y*=iv;
            S[t][0]=La; S[t][1]=Lb; S[t][2]=Lc; S[t][3]=Ld;
        }
    }
    __syncthreads();

    // exclusive prefix = inclusive of thread t-1
    float2 Ea = make_float2(1.f,0.f), Eb = make_float2(0.f,0.f);
    float2 Ec = make_float2(0.f,0.f), Ed = make_float2(1.f,0.f);
    if (t > 0) { Ea=S[t-1][0]; Eb=S[t-1][1]; Ec=S[t-1][2]; Ed=S[t-1][3]; }
    int i0 = dirb ? (Nc - 1) : 0;
    float2 d0 = make_float2(Vp[i0] + 2.0f, -Gp[i0]);
    float2 vn = cadd(cmul(Ea, d0), Eb);
    float2 vd = cadd(cmul(Ec, d0), Ed);
    // ap = vn / vd
    float dm = __fdividef(1.0f, vd.x*vd.x + vd.y*vd.y);
    float2 ap = make_float2((vn.x*vd.x + vn.y*vd.y) * dm,
                            (vn.y*vd.x - vn.x*vd.y) * dm);
    float2* out = (dirb ? g_b : g_a) + bb * Nc;
    #pragma unroll
    for (int j = 0; j < 8; j++) {
        int idx = t * 8 + j;
        int i = dirb ? (Nc - 1 - idx) : idx;
        float2 dd = make_float2(Vp[i] + 2.0f, -Gp[i]);
        float2 av;
        if (idx == 0) av = dd;
        else {
            float inv = __fdividef(1.0f, ap.x*ap.x + ap.y*ap.y);
            av = make_float2(dd.x - ap.x*inv, dd.y + ap.y*inv);
        }
        out[i] = av;
        ap = av;
    }
}

// ---------------- K3: G = 1/(a+b-d) -> features ; also decay precompute -------
__global__ void feat_kernel() {
    int i = blockIdx.x * blockDim.x + threadIdx.x;   // 8192 total
    float2 a = g_a[i], b = g_b[i];
    float dr = g_V[i] + 2.0f, di = -g_gamma[i];
    float er = a.x + b.x - dr;
    float ei = a.y + b.y - di;
    float m = __fdividef(1.0f, er * er + ei * ei);
    g_feat[i] = make_float2(er * m, -ei * m);
    g_decay[i] = __expf(-g_gamma[i] * 0.01f);
}

// ---------------- K4: x1 = x + feat@w_bk + b_bk ; LN2 -> g_xn ----------------
__global__ void bk_ln2_kernel(const float* __restrict__ x,
                              const float* __restrict__ wbk, const float* __restrict__ bbk,
                              const float* __restrict__ g2, const float* __restrict__ b2) {
    int r = blockIdx.x, t = threadIdx.x;
    float2 f = g_feat[r];
    const float4 xv = *(const float4*)(x + (size_t)r * Dc + t * 4);
    float4 w0 = *(const float4*)(wbk + t * 4);
    float4 w1 = *(const float4*)(wbk + Dc + t * 4);
    float4 bb = *(const float4*)(bbk + t * 4);
    float4 v;
    v.x = xv.x + f.x * w0.x + f.y * w1.x + bb.x;
    v.y = xv.y + f.x * w0.y + f.y * w1.y + bb.y;
    v.z = xv.z + f.x * w0.z + f.y * w1.z + bb.z;
    v.w = xv.w + f.x * w0.w + f.y * w1.w + bb.w;
    *(float4*)(g_x1 + (size_t)r * Dc + t * 4) = v;
    float s  = v.x + v.y + v.z + v.w;
    float ss = v.x*v.x + v.y*v.y + v.z*v.z + v.w*v.w;
    float2 red = blockReduce2(s, ss);
    float mean = red.x * (1.0f / Dc);
    float var  = red.y * (1.0f / Dc) - mean * mean;
    float rstd = rsqrtf(var + 1e-5f);
    float4 gv = *(const float4*)(g2 + t * 4);
    float4 bv = *(const float4*)(b2 + t * 4);
    float4 o;
    o.x = (v.x - mean) * rstd * gv.x + bv.x;
    o.y = (v.y - mean) * rstd * gv.y + bv.y;
    o.z = (v.z - mean) * rstd * gv.z + bv.z;
    o.w = (v.w - mean) * rstd * gv.w + bv.w;
    *(float4*)(g_xn + (size_t)r * Dc + t * 4) = o;
}

// ---------------- generic LN (for LN3) ----------------
__global__ void ln_kernel(const float* __restrict__ X,
                          const float* __restrict__ g, const float* __restrict__ b,
                          float* __restrict__ out) {
    int r = blockIdx.x, t = threadIdx.x;
    const float4 xv = *(const float4*)(X + (size_t)r * Dc + t * 4);
    float s  = xv.x + xv.y + xv.z + xv.w;
    float ss = xv.x*xv.x + xv.y*xv.y + xv.z*xv.z + xv.w*xv.w;
    float2 red = blockReduce2(s, ss);
    float mean = red.x * (1.0f / Dc);
    float var  = red.y * (1.0f / Dc) - mean * mean;
    float rstd = rsqrtf(var + 1e-5f);
    float4 gv = *(const float4*)(g + t * 4);
    float4 bv = *(const float4*)(b + t * 4);
    float4 o;
    o.x = (xv.x - mean) * rstd * gv.x + bv.x;
    o.y = (xv.y - mean) * rstd * gv.y + bv.y;
    o.z = (xv.z - mean) * rstd * gv.z + bv.z;
    o.w = (xv.w - mean) * rstd * gv.w + bv.w;
    *(float4*)(out + (size_t)r * Dc + t * 4) = o;
}

// ---------------- FP16 tensor-core GEMM (double-buffered, m16n8k16) ----------------
template<int ACT, int RES>
__global__ __launch_bounds__(256)
void h16_gemm_kernel(const float* __restrict__ A, const float* __restrict__ Bm,
                     const float* __restrict__ bias, const float* __restrict__ Rm,
                     float* __restrict__ C, int M, int Nn, int K) {
    __shared__ unsigned As2[2][8][136];   // [stage][k2][m]  (half2: lo=even k, hi=odd k)
    __shared__ unsigned Bs2[2][8][136];   // [stage][k2][n]
    int tid = threadIdx.x;
    int brow = blockIdx.y * 128;
    int bcol = blockIdx.x * 128;
    int wid = tid >> 5, lane = tid & 31;
    int wm = wid & 3, wn = wid >> 2;
    int m_base = wm * 32, n_base = wn * 64;
    int g = lane >> 2, c = lane & 3;

    float acc[2][8][4];
    #pragma unroll
    for (int mt = 0; mt < 2; mt++)
        #pragma unroll
        for (int nt = 0; nt < 8; nt++)
            #pragma unroll
            for (int i = 0; i < 4; i++) acc[mt][nt][i] = 0.0f;

    int ar  = tid >> 1;
    int akq = (tid & 1) * 8;
    const float* aptr = A + (size_t)(brow + ar) * K + akq;
    int bk2 = tid >> 5;
    int bn  = (tid & 31) * 4;
    const float* bptr = Bm + (size_t)(2 * bk2) * Nn + bcol + bn;

    {
        float4 av0 = *(const float4*)(aptr);
        float4 av1 = *(const float4*)(aptr + 4);
        int k2b = akq >> 1;
        As2[0][k2b + 0][ar] = pack_h2(av0.x, av0.y);
        As2[0][k2b + 1][ar] = pack_h2(av0.z, av0.w);
        As2[0][k2b + 2][ar] = pack_h2(av1.x, av1.y);
        As2[0][k2b + 3][ar] = pack_h2(av1.z, av1.w);
        float4 bv0 = *(const float4*)(bptr);
        float4 bv1 = *(const float4*)(bptr + Nn);
        uint4 bs = make_uint4(pack_h2(bv0.x, bv1.x), pack_h2(bv0.y, bv1.y),
                              pack_h2(bv0.z, bv1.z), pack_h2(bv0.w, bv1.w));
        *(uint4*)&Bs2[0][bk2][bn] = bs;
    }
    __syncthreads();

    int iters = K >> 4;
    for (int it = 0; it < iters; it++) {
        int cur = it & 1;
        bool has_next = (it + 1 < iters);
        float4 av0, av1, bv0, bv1;
        if (has_next) {
            int k0 = (it + 1) << 4;
            av0 = *(const float4*)(aptr + k0);
            av1 = *(const float4*)(aptr + k0 + 4);
            bv0 = *(const float4*)(bptr + (size_t)k0 * Nn);
            bv1 = *(const float4*)(bptr + (size_t)(k0 + 1) * Nn);
        }

        unsigned afr[2][4];
        #pragma unroll
        for (int mt = 0; mt < 2; mt++) {
            int mr = m_base + mt * 16 + g;
            afr[mt][0] = As2[cur][c][mr];
            afr[mt][1] = As2[cur][c][mr + 8];
            afr[mt][2] = As2[cur][c + 4][mr];
            afr[mt][3] = As2[cur][c + 4][mr + 8];
        }
        unsigned bfr[8][2];
        #pragma unroll
        for (int nt = 0; nt < 8; nt++) {
            int nc = n_base + nt * 8 + g;
            bfr[nt][0] = Bs2[cur][c][nc];
            bfr[nt][1] = Bs2[cur][c + 4][nc];
        }
        #pragma unroll
        for (int mt = 0; mt < 2; mt++)
            #pragma unroll
            for (int nt = 0; nt < 8; nt++)
                mma_f16(acc[mt][nt], afr[mt], bfr[nt]);

        if (has_next) {
            int nxt = (it + 1) & 1;
            int k2b = akq >> 1;
            As2[nxt][k2b + 0][ar] = pack_h2(av0.x, av0.y);
            As2[nxt][k2b + 1][ar] = pack_h2(av0.z, av0.w);
            As2[nxt][k2b + 2][ar] = pack_h2(av1.x, av1.y);
            As2[nxt][k2b + 3][ar] = pack_h2(av1.z, av1.w);
            uint4 bs = make_uint4(pack_h2(bv0.x, bv1.x), pack_h2(bv0.y, bv1.y),
                                  pack_h2(bv0.z, bv1.z), pack_h2(bv0.w, bv1.w));
            *(uint4*)&Bs2[nxt][bk2][bn] = bs;
        }
        __syncthreads();
    }

    // epilogue
    #pragma unroll
    for (int mt = 0; mt < 2; mt++) {
        #pragma unroll
        for (int nt = 0; nt < 8; nt++) {
            int row0 = brow + m_base + mt * 16 + g;
            int col  = bcol + n_base + nt * 8 + 2 * c;
            float b0 = bias[col], b1 = bias[col + 1];
            #pragma unroll
            for (int h = 0; h < 2; h++) {
                int row = row0 + h * 8;
                float v0 = acc[mt][nt][2 * h]     + b0;
                float v1 = acc[mt][nt][2 * h + 1] + b1;
                if (ACT) { v0 = gelu_tanh(v0); v1 = gelu_tanh(v1); }
                if (RES) {
                    const float2 rv = *(const float2*)(Rm + (size_t)row * Nn + col);
                    v0 += rv.x; v1 += rv.y;
                }
                float2 o = make_float2(v0, v1);
                *(float2*)(C + (size_t)row * Nn + col) = o;
            }
        }
    }
}

// ---------------- Hebbian fast-weight scan (4-slot register pipeline) ----------
// grid 128 blocks: (bh = blockIdx.x>>2, colgroup = blockIdx.x&3), 128 threads.
// Each warp owns 4 columns; each lane: 8 rows x 1 column of W in registers.
// Prefetch distance 3 steps to cover L2 latency; decay preloaded from g_decay.
__global__ void __launch_bounds__(128) hebbian_kernel() {
    int bx = blockIdx.x;
    int bh = bx >> 2, cg = bx & 3;
    int b = bh >> 3, h = bh & 7;
    int tid = threadIdx.x;
    int w = tid >> 5, lane = tid & 31;
    int e  = cg * 16 + w * 4 + (lane & 3);
    int d0 = (lane >> 2) * 8;
    const float* base = g_qkv + (size_t)b * Nc * QKVW;
    const float* dcp  = g_decay + b * Nc;
    float W[8];
    #pragma unroll
    for (int i = 0; i < 8; i++) W[i] = 0.0f;

    float4 q0s[4], q1s[4], k0s[4], k1s[4];
    float vvs[4], dcs[4];
    #pragma unroll
    for (int s = 0; s < 3; s++) {
        const float* nb = base + (size_t)s * QKVW;
        q0s[s] = *(const float4*)(nb + h * 64 + d0);
        q1s[s] = *(const float4*)(nb + h * 64 + d0 + 4);
        k0s[s] = *(const float4*)(nb + 512 + h * 64 + d0);
        k1s[s] = *(const float4*)(nb + 512 + h * 64 + d0 + 4);
        vvs[s] = *(nb + 1024 + h * 64 + e);
        dcs[s] = dcp[s];
    }
    float* outp = g_heb + (size_t)b * Nc * HEBW + h * 64 + e;

    #pragma unroll 4
    for (int t = 0; t < Nc; t++) {
        int s = t & 3;
        int tp = t + 3;
        if (tp < Nc) {
            int s2 = tp & 3;
            const float* nb = base + (size_t)tp * QKVW;
            q0s[s2] = *(const float4*)(nb + h * 64 + d0);
            q1s[s2] = *(const float4*)(nb + h * 64 + d0 + 4);
            k0s[s2] = *(const float4*)(nb + 512 + h * 64 + d0);
            k1s[s2] = *(const float4*)(nb + 512 + h * 64 + d0 + 4);
            vvs[s2] = *(nb + 1024 + h * 64 + e);
            dcs[s2] = dcp[tp];
        }
        float dec = dcs[s];
        float ev  = 0.1f * vvs[s];
        float4 cq0 = q0s[s], cq1 = q1s[s], ck0 = k0s[s], ck1 = k1s[s];
        W[0] = fmaf(dec, W[0], ck0.x * ev);
        W[1] = fmaf(dec, W[1], ck0.y * ev);
        W[2] = fmaf(dec, W[2], ck0.z * ev);
        W[3] = fmaf(dec, W[3], ck0.w * ev);
        W[4] = fmaf(dec, W[4], ck1.x * ev);
        W[5] = fmaf(dec, W[5], ck1.y * ev);
        W[6] = fmaf(dec, W[6], ck1.z * ev);
        W[7] = fmaf(dec, W[7], ck1.w * ev);
        float p0 = cq0.x * W[0];
        p0 = fmaf(cq0.y, W[1], p0);
        p0 = fmaf(cq0.z, W[2], p0);
        p0 = fmaf(cq0.w, W[3], p0);
        float p1 = cq1.x * W[4];
        p1 = fmaf(cq1.y, W[5], p1);
        p1 = fmaf(cq1.z, W[6], p1);
        p1 = fmaf(cq1.w, W[7], p1);
        float p = p0 + p1;
        p += __shfl_xor_sync(0xffffffffu, p, 4);
        p += __shfl_xor_sync(0xffffffffu, p, 8);
        p += __shfl_xor_sync(0xffffffffu, p, 16);
        if ((lane >> 2) == 0) outp[(size_t)t * HEBW] = p;
    }
}

// ---------------- host launcher ----------------
extern "C" void kernel_launch(void* const* d_in, const int* in_sizes, int n_in,
                              void* d_out, int out_size) {
    const float* x     = (const float*)d_in[0];
    const float* ln1_g = (const float*)d_in[1];
    const float* ln1_b = (const float*)d_in[2];
    const float* ln2_g = (const float*)d_in[3];
    const float* ln2_b = (const float*)d_in[4];
    const float* ln3_g = (const float*)d_in[5];
    const float* ln3_b = (const float*)d_in[6];
    const float* w_pot = (const float*)d_in[7];
    const float* b_pot = (const float*)d_in[8];
    const float* w_bk  = (const float*)d_in[9];
    const float* b_bk  = (const float*)d_in[10];
    const float* w_qkv = (const float*)d_in[11];
    const float* b_qkv = (const float*)d_in[12];
    const float* w_out = (const float*)d_in[13];
    const float* b_out = (const float*)d_in[14];
    const float* w_ff1 = (const float*)d_in[15];
    const float* b_ff1 = (const float*)d_in[16];
    const float* w_ff2 = (const float*)d_in[17];
    const float* b_ff2 = (const float*)d_in[18];

    float *pX1, *pXN, *pQKV, *pHEB, *pX2, *pFF;
    cudaGetSymbolAddress((void**)&pX1,  g_x1);
    cudaGetSymbolAddress((void**)&pXN,  g_xn);
    cudaGetSymbolAddress((void**)&pQKV, g_qkv);
    cudaGetSymbolAddress((void**)&pHEB, g_heb);
    cudaGetSymbolAddress((void**)&pX2,  g_x2);
    cudaGetSymbolAddress((void**)&pFF,  g_ffbuf);

    // 1. LN1 + potential head
    ln1_pot_kernel<<<ROWS, 256>>>(x, ln1_g, ln1_b, w_pot, b_pot);
    // 2. continued-fraction scans (parallel Mobius scan; 4 fwd + 4 bwd blocks)
    cf_scan_par_kernel<<<8, 256>>>();
    // 3. Green-function diagonal features + decay precompute
    feat_kernel<<<32, 256>>>();
    // 4. rank-2 injection + LN2
    bk_ln2_kernel<<<ROWS, 256>>>(x, w_bk, b_bk, ln2_g, ln2_b);
    // 5. QKV projection (fp16 tensor cores)
    h16_gemm_kernel<0, 0><<<dim3(QKVW / 128, ROWS / 128), 256>>>(
        pXN, w_qkv, b_qkv, nullptr, pQKV, ROWS, QKVW, Dc);
    // 6. Hebbian fast-weight scan
    hebbian_kernel<<<128, 128>>>();
    // 7. out-projection + residual(x1)
    h16_gemm_kernel<0, 1><<<dim3(Dc / 128, ROWS / 128), 256>>>(
        pHEB, w_out, b_out, pX1, pX2, ROWS, Dc, HEBW);
    // 8. LN3
    ln_kernel<<<ROWS, 256>>>(pX2, ln3_g, ln3_b, pXN);
    // 9. FFN up + gelu
    h16_gemm_kernel<1, 0><<<dim3(FFc / 128, ROWS / 128), 256>>>(
        pXN, w_ff1, b_ff1, nullptr, pFF, ROWS, FFc, Dc);
    // 10. FFN down + residual(x2) -> output
    h16_gemm_kernel<0, 1><<<dim3(Dc / 128, ROWS / 128), 256>>>(
        pFF, w_ff2, b_ff2, pX2, (float*)d_out, ROWS, Dc, FFc);
}

// round 17
// speedup vs baseline: 4.2315x; 1.3999x over previous
#include <cuda_runtime.h>
#include <cuda_fp16.h>
#include <math.h>

// Problem constants
#define Bc 4
#define Nc 2048
#define Dc 1024
#define Hc 8
#define HDc 64
#define FFc 4096
#define ROWS (Bc*Nc)            // 8192
#define QKVW (3*Hc*HDc)         // 1536
#define HEBW (Hc*HDc)           // 512

// ---------------- scratch (device globals; no allocs allowed) ----------------
__device__ __align__(16) float  g_V[ROWS];
__device__ __align__(16) float  g_gamma[ROWS];
__device__ __align__(16) float  g_decay[ROWS];
__device__ __align__(16) float2 g_a[ROWS];
__device__ __align__(16) float2 g_b[ROWS];
__device__ __align__(16) float2 g_feat[ROWS];
__device__ __align__(16) float  g_x1[(size_t)ROWS*Dc];
__device__ __align__(16) float  g_qkv[(size_t)ROWS*QKVW];
__device__ __align__(16) float  g_x2[(size_t)ROWS*Dc];
// fp16 activation buffers (producers already apply the GEMM's input rounding)
__device__ __align__(16) __half g_xnh[(size_t)ROWS*Dc];
__device__ __align__(16) __half g_hebh[(size_t)ROWS*HEBW];
__device__ __align__(16) __half g_ffh[(size_t)ROWS*FFc];
// fp16 packed weights: [K/2][N] of half2 (lo = even k, hi = odd k)
__device__ __align__(16) unsigned g_wh_qkv[(size_t)(Dc/2)*QKVW];
__device__ __align__(16) unsigned g_wh_out[(size_t)(HEBW/2)*Dc];
__device__ __align__(16) unsigned g_wh_ff1[(size_t)(Dc/2)*FFc];
__device__ __align__(16) unsigned g_wh_ff2[(size_t)(FFc/2)*Dc];

// ---------------- helpers ----------------
__device__ __forceinline__ float2 blockReduce2(float a, float b) {
    // blockDim.x == 256
    #pragma unroll
    for (int off = 16; off > 0; off >>= 1) {
        a += __shfl_down_sync(0xffffffffu, a, off);
        b += __shfl_down_sync(0xffffffffu, b, off);
    }
    __shared__ float sa[8], sb[8];
    int w = threadIdx.x >> 5, l = threadIdx.x & 31;
    __syncthreads();
    if (l == 0) { sa[w] = a; sb[w] = b; }
    __syncthreads();
    if (threadIdx.x == 0) {
        float ta = sa[0], tb = sb[0];
        #pragma unroll
        for (int i = 1; i < 8; i++) { ta += sa[i]; tb += sb[i]; }
        sa[0] = ta; sb[0] = tb;
    }
    __syncthreads();
    return make_float2(sa[0], sb[0]);
}

__device__ __forceinline__ float gelu_tanh(float v) {
    const float c = 0.7978845608028654f;
    float t = tanhf(c * (v + 0.044715f * v * v * v));
    return 0.5f * v * (1.0f + t);
}

__device__ __forceinline__ unsigned pack_h2(float lo, float hi) {
    __half2 h = __floats2half2_rn(lo, hi);   // .x = lo (low half), .y = hi
    return *reinterpret_cast<unsigned*>(&h);
}

__device__ __forceinline__ void mma_f16(float* d, const unsigned* a, const unsigned* b) {
    asm volatile(
        "mma.sync.aligned.m16n8k16.row.col.f32.f16.f16.f32 "
        "{%0,%1,%2,%3}, {%4,%5,%6,%7}, {%8,%9}, {%0,%1,%2,%3};"
        : "+f"(d[0]), "+f"(d[1]), "+f"(d[2]), "+f"(d[3])
        : "r"(a[0]), "r"(a[1]), "r"(a[2]), "r"(a[3]), "r"(b[0]), "r"(b[1]));
}

// complex helpers
__device__ __forceinline__ float2 cmul(float2 a, float2 b) {
    return make_float2(a.x*b.x - a.y*b.y, a.x*b.y + a.y*b.x);
}
__device__ __forceinline__ float2 cadd(float2 a, float2 b) {
    return make_float2(a.x+b.x, a.y+b.y);
}
__device__ __forceinline__ float2 csub(float2 a, float2 b) {
    return make_float2(a.x-b.x, a.y-b.y);
}

// ---------------- weight pack: W[K][N] fp32 -> Wp[K/2][N] half2 ----------------
__global__ void pack_w_kernel(const float* __restrict__ W, unsigned* __restrict__ Wp,
                              int N, int total) {
    int i = blockIdx.x * blockDim.x + threadIdx.x;
    if (i >= total) return;
    int k2 = i / N, n = i - k2 * N;
    Wp[i] = pack_h2(W[(size_t)(2 * k2) * N + n], W[(size_t)(2 * k2 + 1) * N + n]);
}

// ---------------- K1: LN1 + potential head -> V, gamma ----------------
__global__ void ln1_pot_kernel(const float* __restrict__ x,
                               const float* __restrict__ g1, const float* __restrict__ b1,
                               const float* __restrict__ wpot, const float* __restrict__ bpot) {
    int r = blockIdx.x, t = threadIdx.x;
    const float4 xv = *(const float4*)(x + (size_t)r * Dc + t * 4);
    float s  = xv.x + xv.y + xv.z + xv.w;
    float ss = xv.x*xv.x + xv.y*xv.y + xv.z*xv.z + xv.w*xv.w;
    float2 red = blockReduce2(s, ss);
    float mean = red.x * (1.0f / Dc);
    float var  = red.y * (1.0f / Dc) - mean * mean;
    float rstd = rsqrtf(var + 1e-5f);
    float4 gv = *(const float4*)(g1 + t * 4);
    float4 bv = *(const float4*)(b1 + t * 4);
    float xn0 = (xv.x - mean) * rstd * gv.x + bv.x;
    float xn1 = (xv.y - mean) * rstd * gv.y + bv.y;
    float xn2 = (xv.z - mean) * rstd * gv.z + bv.z;
    float xn3 = (xv.w - mean) * rstd * gv.w + bv.w;
    // w_pot is (D,2) row-major -> interleaved pairs
    float4 p0 = *(const float4*)(wpot + t * 8);
    float4 p1 = *(const float4*)(wpot + t * 8 + 4);
    float a0 = xn0 * p0.x + xn1 * p0.z + xn2 * p1.x + xn3 * p1.z;
    float a1 = xn0 * p0.y + xn1 * p0.w + xn2 * p1.y + xn3 * p1.w;
    float2 pr = blockReduce2(a0, a1);
    if (t == 0) {
        float Vv   = pr.x + bpot[0];
        float praw = pr.y + bpot[1];
        float sp = fmaxf(praw, 0.0f) + log1pf(__expf(-fabsf(praw)));
        g_V[r]     = Vv;
        g_gamma[r] = sp + 0.1f;
    }
}

// ---------------- K2: continued-fraction scans (parallel Mobius scan) ----------------
__global__ void __launch_bounds__(256) cf_scan_par_kernel() {
    __shared__ float2 S[256][4];
    int blk = blockIdx.x;            // 0..7
    int bb  = blk & 3;
    int dirb = blk >> 2;             // 0 fwd, 1 bwd
    int t = threadIdx.x;
    const float* Vp = g_V + bb * Nc;
    const float* Gp = g_gamma + bb * Nc;

    float2 La = make_float2(1.f, 0.f), Lb = make_float2(0.f, 0.f);
    float2 Lc = make_float2(0.f, 0.f), Ld = make_float2(1.f, 0.f);
    #pragma unroll
    for (int j = 0; j < 8; j++) {
        int idx = t * 8 + j;
        if (idx == 0) continue;
        int i = dirb ? (Nc - 1 - idx) : idx;
        float2 dd = make_float2(Vp[i] + 2.0f, -Gp[i]);
        float2 na = csub(cmul(dd, La), Lc);
        float2 nb = csub(cmul(dd, Lb), Ld);
        Lc = La; Ld = Lb; La = na; Lb = nb;
    }
    {   // normalize
        float nm = fmaxf(fmaxf(fabsf(La.x)+fabsf(La.y), fabsf(Lb.x)+fabsf(Lb.y)),
                         fmaxf(fabsf(Lc.x)+fabsf(Lc.y), fabsf(Ld.x)+fabsf(Ld.y)));
        float iv = __fdividef(1.0f, fmaxf(nm, 1e-30f));
        La.x*=iv; La.y*=iv; Lb.x*=iv; Lb.y*=iv; Lc.x*=iv; Lc.y*=iv; Ld.x*=iv; Ld.y*=iv;
    }
    S[t][0]=La; S[t][1]=Lb; S[t][2]=Lc; S[t][3]=Ld;

    for (int off = 1; off < 256; off <<= 1) {
        __syncthreads();
        float2 Pa, Pb, Pc, Pd;
        bool has = (t >= off);
        if (has) { Pa=S[t-off][0]; Pb=S[t-off][1]; Pc=S[t-off][2]; Pd=S[t-off][3]; }
        __syncthreads();
        if (has) {
            float2 na = cadd(cmul(La,Pa), cmul(Lb,Pc));
            float2 nb = cadd(cmul(La,Pb), cmul(Lb,Pd));
            float2 nc = cadd(cmul(Lc,Pa), cmul(Ld,Pc));
            float2 nd = cadd(cmul(Lc,Pb), cmul(Ld,Pd));
            La=na; Lb=nb; Lc=nc; Ld=nd;
            float nm = fmaxf(fmaxf(fabsf(La.x)+fabsf(La.y), fabsf(Lb.x)+fabsf(Lb.y)),
                             fmaxf(fabsf(Lc.x)+fabsf(Lc.y), fabsf(Ld.x)+fabsf(Ld.y)));
            float iv = __fdividef(1.0f, fmaxf(nm, 1e-30f));
            La.x*=iv; La.y*=iv; Lb.x*=iv; Lb.y*=iv; Lc.x*=iv; Lc.y*=iv; Ld.x*=iv; Ld.y*=iv;
            S[t][0]=La; S[t][1]=Lb; S[t][2]=Lc; S[t][3]=Ld;
        }
    }
    __syncthreads();

    float2 Ea = make_float2(1.f,0.f), Eb = make_float2(0.f,0.f);
    float2 Ec = make_float2(0.f,0.f), Ed = make_float2(1.f,0.f);
    if (t > 0) { Ea=S[t-1][0]; Eb=S[t-1][1]; Ec=S[t-1][2]; Ed=S[t-1][3]; }
    int i0 = dirb ? (Nc - 1) : 0;
    float2 d0 = make_float2(Vp[i0] + 2.0f, -Gp[i0]);
    float2 vn = cadd(cmul(Ea, d0), Eb);
    float2 vd = cadd(cmul(Ec, d0), Ed);
    float dm = __fdividef(1.0f, vd.x*vd.x + vd.y*vd.y);
    float2 ap = make_float2((vn.x*vd.x + vn.y*vd.y) * dm,
                            (vn.y*vd.x - vn.x*vd.y) * dm);
    float2* out = (dirb ? g_b : g_a) + bb * Nc;
    #pragma unroll
    for (int j = 0; j < 8; j++) {
        int idx = t * 8 + j;
        int i = dirb ? (Nc - 1 - idx) : idx;
        float2 dd = make_float2(Vp[i] + 2.0f, -Gp[i]);
        float2 av;
        if (idx == 0) av = dd;
        else {
            float inv = __fdividef(1.0f, ap.x*ap.x + ap.y*ap.y);
            av = make_float2(dd.x - ap.x*inv, dd.y + ap.y*inv);
        }
        out[i] = av;
        ap = av;
    }
}

// ---------------- K3: G = 1/(a+b-d) -> features ; also decay precompute -------
__global__ void feat_kernel() {
    int i = blockIdx.x * blockDim.x + threadIdx.x;   // 8192 total
    float2 a = g_a[i], b = g_b[i];
    float dr = g_V[i] + 2.0f, di = -g_gamma[i];
    float er = a.x + b.x - dr;
    float ei = a.y + b.y - di;
    float m = __fdividef(1.0f, er * er + ei * ei);
    g_feat[i] = make_float2(er * m, -ei * m);
    g_decay[i] = __expf(-g_gamma[i] * 0.01f);
}

// ---------------- K4: x1 = x + feat@w_bk + b_bk ; LN2 -> g_xnh (fp16) ---------
__global__ void bk_ln2_kernel(const float* __restrict__ x,
                              const float* __restrict__ wbk, const float* __restrict__ bbk,
                              const float* __restrict__ g2, const float* __restrict__ b2) {
    int r = blockIdx.x, t = threadIdx.x;
    float2 f = g_feat[r];
    const float4 xv = *(const float4*)(x + (size_t)r * Dc + t * 4);
    float4 w0 = *(const float4*)(wbk + t * 4);
    float4 w1 = *(const float4*)(wbk + Dc + t * 4);
    float4 bb = *(const float4*)(bbk + t * 4);
    float4 v;
    v.x = xv.x + f.x * w0.x + f.y * w1.x + bb.x;
    v.y = xv.y + f.x * w0.y + f.y * w1.y + bb.y;
    v.z = xv.z + f.x * w0.z + f.y * w1.z + bb.z;
    v.w = xv.w + f.x * w0.w + f.y * w1.w + bb.w;
    *(float4*)(g_x1 + (size_t)r * Dc + t * 4) = v;
    float s  = v.x + v.y + v.z + v.w;
    float ss = v.x*v.x + v.y*v.y + v.z*v.z + v.w*v.w;
    float2 red = blockReduce2(s, ss);
    float mean = red.x * (1.0f / Dc);
    float var  = red.y * (1.0f / Dc) - mean * mean;
    float rstd = rsqrtf(var + 1e-5f);
    float4 gv = *(const float4*)(g2 + t * 4);
    float4 bv = *(const float4*)(b2 + t * 4);
    uint2 o;
    o.x = pack_h2((v.x - mean) * rstd * gv.x + bv.x, (v.y - mean) * rstd * gv.y + bv.y);
    o.y = pack_h2((v.z - mean) * rstd * gv.z + bv.z, (v.w - mean) * rstd * gv.w + bv.w);
    *(uint2*)(g_xnh + (size_t)r * Dc + t * 4) = o;
}

// ---------------- generic LN (for LN3): fp32 in -> fp16 out -------------------
__global__ void ln_kernel(const float* __restrict__ X,
                          const float* __restrict__ g, const float* __restrict__ b,
                          __half* __restrict__ out) {
    int r = blockIdx.x, t = threadIdx.x;
    const float4 xv = *(const float4*)(X + (size_t)r * Dc + t * 4);
    float s  = xv.x + xv.y + xv.z + xv.w;
    float ss = xv.x*xv.x + xv.y*xv.y + xv.z*xv.z + xv.w*xv.w;
    float2 red = blockReduce2(s, ss);
    float mean = red.x * (1.0f / Dc);
    float var  = red.y * (1.0f / Dc) - mean * mean;
    float rstd = rsqrtf(var + 1e-5f);
    float4 gv = *(const float4*)(g + t * 4);
    float4 bv = *(const float4*)(b + t * 4);
    uint2 o;
    o.x = pack_h2((xv.x - mean) * rstd * gv.x + bv.x, (xv.y - mean) * rstd * gv.y + bv.y);
    o.y = pack_h2((xv.z - mean) * rstd * gv.z + bv.z, (xv.w - mean) * rstd * gv.w + bv.w);
    *(uint2*)(out + (size_t)r * Dc + t * 4) = o;
}

// ---------------- FP16 tensor-core GEMM (double-buffered, m16n8k16) -----------
// A: fp16 row-major [M][K]; Bp: packed half2 [K/2][N]; all cvts pre-hoisted.
// C = A @ B + bias, optional GELU, optional +R(fp32); OUTH: fp16 or fp32 out.
template<int ACT, int RES, int OUTH>
__global__ __launch_bounds__(256)
void h16_gemm_kernel(const __half* __restrict__ A, const unsigned* __restrict__ Bp,
                     const float* __restrict__ bias, const float* __restrict__ Rm,
                     void* __restrict__ Cv, int M, int Nn, int K) {
    __shared__ unsigned As2[2][8][136];   // [stage][k2][m]
    __shared__ unsigned Bs2[2][8][136];   // [stage][k2][n]
    int tid = threadIdx.x;
    int brow = blockIdx.y * 128;
    int bcol = blockIdx.x * 128;
    int wid = tid >> 5, lane = tid & 31;
    int wm = wid & 3, wn = wid >> 2;
    int m_base = wm * 32, n_base = wn * 64;
    int g = lane >> 2, c = lane & 3;

    float acc[2][8][4];
    #pragma unroll
    for (int mt = 0; mt < 2; mt++)
        #pragma unroll
        for (int nt = 0; nt < 8; nt++)
            #pragma unroll
            for (int i = 0; i < 4; i++) acc[mt][nt][i] = 0.0f;

    int ar  = tid >> 1;
    int akq = (tid & 1) * 8;        // half offset within row; k2 base = akq/2
    int k2b = akq >> 1;
    const __half* aptr = A + (size_t)(brow + ar) * K + akq;
    int bk2 = tid >> 5;
    int bn  = (tid & 31) * 4;
    const unsigned* bptr = Bp + (size_t)bk2 * Nn + bcol + bn;

    {
        uint4 av = *(const uint4*)(aptr);
        As2[0][k2b + 0][ar] = av.x;
        As2[0][k2b + 1][ar] = av.y;
        As2[0][k2b + 2][ar] = av.z;
        As2[0][k2b + 3][ar] = av.w;
        uint4 bv = *(const uint4*)(bptr);
        *(uint4*)&Bs2[0][bk2][bn] = bv;
    }
    __syncthreads();

    int iters = K >> 4;
    for (int it = 0; it < iters; it++) {
        int cur = it & 1;
        bool has_next = (it + 1 < iters);
        uint4 av, bv;
        if (has_next) {
            int k0 = (it + 1) << 4;
            av = *(const uint4*)(aptr + k0);
            bv = *(const uint4*)(bptr + (size_t)(k0 >> 1) * Nn);
        }

        unsigned afr[2][4];
        #pragma unroll
        for (int mt = 0; mt < 2; mt++) {
            int mr = m_base + mt * 16 + g;
            afr[mt][0] = As2[cur][c][mr];
            afr[mt][1] = As2[cur][c][mr + 8];
            afr[mt][2] = As2[cur][c + 4][mr];
            afr[mt][3] = As2[cur][c + 4][mr + 8];
        }
        unsigned bfr[8][2];
        #pragma unroll
        for (int nt = 0; nt < 8; nt++) {
            int nc = n_base + nt * 8 + g;
            bfr[nt][0] = Bs2[cur][c][nc];
            bfr[nt][1] = Bs2[cur][c + 4][nc];
        }
        #pragma unroll
        for (int mt = 0; mt < 2; mt++)
            #pragma unroll
            for (int nt = 0; nt < 8; nt++)
                mma_f16(acc[mt][nt], afr[mt], bfr[nt]);

        if (has_next) {
            int nxt = (it + 1) & 1;
            As2[nxt][k2b + 0][ar] = av.x;
            As2[nxt][k2b + 1][ar] = av.y;
            As2[nxt][k2b + 2][ar] = av.z;
            As2[nxt][k2b + 3][ar] = av.w;
            *(uint4*)&Bs2[nxt][bk2][bn] = bv;
        }
        __syncthreads();
    }

    // epilogue
    #pragma unroll
    for (int mt = 0; mt < 2; mt++) {
        #pragma unroll
        for (int nt = 0; nt < 8; nt++) {
            int row0 = brow + m_base + mt * 16 + g;
            int col  = bcol + n_base + nt * 8 + 2 * c;
            float b0 = bias[col], b1 = bias[col + 1];
            #pragma unroll
            for (int h = 0; h < 2; h++) {
                int row = row0 + h * 8;
                float v0 = acc[mt][nt][2 * h]     + b0;
                float v1 = acc[mt][nt][2 * h + 1] + b1;
                if (ACT) { v0 = gelu_tanh(v0); v1 = gelu_tanh(v1); }
                if (RES) {
                    const float2 rv = *(const float2*)(Rm + (size_t)row * Nn + col);
                    v0 += rv.x; v1 += rv.y;
                }
                if (OUTH) {
                    *(unsigned*)((__half*)Cv + (size_t)row * Nn + col) = pack_h2(v0, v1);
                } else {
                    *(float2*)((float*)Cv + (size_t)row * Nn + col) = make_float2(v0, v1);
                }
            }
        }
    }
}

// ---------------- Hebbian fast-weight scan (4-slot register pipeline) ----------
__global__ void __launch_bounds__(128) hebbian_kernel() {
    int bx = blockIdx.x;
    int bh = bx >> 2, cg = bx & 3;
    int b = bh >> 3, h = bh & 7;
    int tid = threadIdx.x;
    int w = tid >> 5, lane = tid & 31;
    int e  = cg * 16 + w * 4 + (lane & 3);
    int d0 = (lane >> 2) * 8;
    const float* base = g_qkv + (size_t)b * Nc * QKVW;
    const float* dcp  = g_decay + b * Nc;
    float W[8];
    #pragma unroll
    for (int i = 0; i < 8; i++) W[i] = 0.0f;

    float4 q0s[4], q1s[4], k0s[4], k1s[4];
    float vvs[4], dcs[4];
    #pragma unroll
    for (int s = 0; s < 3; s++) {
        const float* nb = base + (size_t)s * QKVW;
        q0s[s] = *(const float4*)(nb + h * 64 + d0);
        q1s[s] = *(const float4*)(nb + h * 64 + d0 + 4);
        k0s[s] = *(const float4*)(nb + 512 + h * 64 + d0);
        k1s[s] = *(const float4*)(nb + 512 + h * 64 + d0 + 4);
        vvs[s] = *(nb + 1024 + h * 64 + e);
        dcs[s] = dcp[s];
    }
    __half* outp = g_hebh + (size_t)b * Nc * HEBW + h * 64 + e;

    #pragma unroll 4
    for (int t = 0; t < Nc; t++) {
        int s = t & 3;
        int tp = t + 3;
        if (tp < Nc) {
            int s2 = tp & 3;
            const float* nb = base + (size_t)tp * QKVW;
            q0s[s2] = *(const float4*)(nb + h * 64 + d0);
            q1s[s2] = *(const float4*)(nb + h * 64 + d0 + 4);
            k0s[s2] = *(const float4*)(nb + 512 + h * 64 + d0);
            k1s[s2] = *(const float4*)(nb + 512 + h * 64 + d0 + 4);
            vvs[s2] = *(nb + 1024 + h * 64 + e);
            dcs[s2] = dcp[tp];
        }
        float dec = dcs[s];
        float ev  = 0.1f * vvs[s];
        float4 cq0 = q0s[s], cq1 = q1s[s], ck0 = k0s[s], ck1 = k1s[s];
        W[0] = fmaf(dec, W[0], ck0.x * ev);
        W[1] = fmaf(dec, W[1], ck0.y * ev);
        W[2] = fmaf(dec, W[2], ck0.z * ev);
        W[3] = fmaf(dec, W[3], ck0.w * ev);
        W[4] = fmaf(dec, W[4], ck1.x * ev);
        W[5] = fmaf(dec, W[5], ck1.y * ev);
        W[6] = fmaf(dec, W[6], ck1.z * ev);
        W[7] = fmaf(dec, W[7], ck1.w * ev);
        float p0 = cq0.x * W[0];
        p0 = fmaf(cq0.y, W[1], p0);
        p0 = fmaf(cq0.z, W[2], p0);
        p0 = fmaf(cq0.w, W[3], p0);
        float p1 = cq1.x * W[4];
        p1 = fmaf(cq1.y, W[5], p1);
        p1 = fmaf(cq1.z, W[6], p1);
        p1 = fmaf(cq1.w, W[7], p1);
        float p = p0 + p1;
        p += __shfl_xor_sync(0xffffffffu, p, 4);
        p += __shfl_xor_sync(0xffffffffu, p, 8);
        p += __shfl_xor_sync(0xffffffffu, p, 16);
        if ((lane >> 2) == 0) outp[(size_t)t * HEBW] = __float2half_rn(p);
    }
}

// ---------------- host launcher ----------------
extern "C" void kernel_launch(void* const* d_in, const int* in_sizes, int n_in,
                              void* d_out, int out_size) {
    const float* x     = (const float*)d_in[0];
    const float* ln1_g = (const float*)d_in[1];
    const float* ln1_b = (const float*)d_in[2];
    const float* ln2_g = (const float*)d_in[3];
    const float* ln2_b = (const float*)d_in[4];
    const float* ln3_g = (const float*)d_in[5];
    const float* ln3_b = (const float*)d_in[6];
    const float* w_pot = (const float*)d_in[7];
    const float* b_pot = (const float*)d_in[8];
    const float* w_bk  = (const float*)d_in[9];
    const float* b_bk  = (const float*)d_in[10];
    const float* w_qkv = (const float*)d_in[11];
    const float* b_qkv = (const float*)d_in[12];
    const float* w_out = (const float*)d_in[13];
    const float* b_out = (const float*)d_in[14];
    const float* w_ff1 = (const float*)d_in[15];
    const float* b_ff1 = (const float*)d_in[16];
    const float* w_ff2 = (const float*)d_in[17];
    const float* b_ff2 = (const float*)d_in[18];

    float *pX1, *pQKV, *pX2;
    __half *pXNH, *pHEBH, *pFFH;
    unsigned *pWQ, *pWO, *pW1, *pW2;
    cudaGetSymbolAddress((void**)&pX1,   g_x1);
    cudaGetSymbolAddress((void**)&pQKV,  g_qkv);
    cudaGetSymbolAddress((void**)&pX2,   g_x2);
    cudaGetSymbolAddress((void**)&pXNH,  g_xnh);
    cudaGetSymbolAddress((void**)&pHEBH, g_hebh);
    cudaGetSymbolAddress((void**)&pFFH,  g_ffh);
    cudaGetSymbolAddress((void**)&pWQ,   g_wh_qkv);
    cudaGetSymbolAddress((void**)&pWO,   g_wh_out);
    cudaGetSymbolAddress((void**)&pW1,   g_wh_ff1);
    cudaGetSymbolAddress((void**)&pW2,   g_wh_ff2);

    // 0. pack weights to fp16 half2 layout (identical rounding to in-GEMM cvt)
    {
        int t1 = (Dc/2)*QKVW, t2 = (HEBW/2)*Dc, t3 = (Dc/2)*FFc, t4 = (FFc/2)*Dc;
        pack_w_kernel<<<(t1+255)/256, 256>>>(w_qkv, pWQ, QKVW, t1);
        pack_w_kernel<<<(t2+255)/256, 256>>>(w_out, pWO, Dc,   t2);
        pack_w_kernel<<<(t3+255)/256, 256>>>(w_ff1, pW1, FFc,  t3);
        pack_w_kernel<<<(t4+255)/256, 256>>>(w_ff2, pW2, Dc,   t4);
    }
    // 1. LN1 + potential head
    ln1_pot_kernel<<<ROWS, 256>>>(x, ln1_g, ln1_b, w_pot, b_pot);
    // 2. continued-fraction scans (parallel Mobius scan; 4 fwd + 4 bwd blocks)
    cf_scan_par_kernel<<<8, 256>>>();
    // 3. Green-function diagonal features + decay precompute
    feat_kernel<<<32, 256>>>();
    // 4. rank-2 injection + LN2 -> fp16
    bk_ln2_kernel<<<ROWS, 256>>>(x, w_bk, b_bk, ln2_g, ln2_b);
    // 5. QKV projection (fp16 in, fp32 out for the scan)
    h16_gemm_kernel<0, 0, 0><<<dim3(QKVW / 128, ROWS / 128), 256>>>(
        pXNH, pWQ, b_qkv, nullptr, pQKV, ROWS, QKVW, Dc);
    // 6. Hebbian fast-weight scan -> fp16
    hebbian_kernel<<<128, 128>>>();
    // 7. out-projection + residual(x1) -> fp32
    h16_gemm_kernel<0, 1, 0><<<dim3(Dc / 128, ROWS / 128), 256>>>(
        pHEBH, pWO, b_out, pX1, pX2, ROWS, Dc, HEBW);
    // 8. LN3 -> fp16
    ln_kernel<<<ROWS, 256>>>(pX2, ln3_g, ln3_b, pXNH);
    // 9. FFN up + gelu -> fp16
    h16_gemm_kernel<1, 0, 1><<<dim3(FFc / 128, ROWS / 128), 256>>>(
        pXNH, pW1, b_ff1, nullptr, pFFH, ROWS, FFc, Dc);
    // 10. FFN down + residual(x2) -> output fp32
    h16_gemm_kernel<0, 1, 0><<<dim3(Dc / 128, ROWS / 128), 256>>>(
        pFFH, pW2, b_ff2, pX2, (float*)d_out, ROWS, Dc, FFc);
}